// round 3
// baseline (speedup 1.0000x reference)
#include <cuda_runtime.h>
#include <cuda_bf16.h>
#include <cstdint>

#define BATCH   16384
#define IN_SIZE 4096
#define NPART   8
#define DDIM    512

#define BM 128
#define BN 128
#define BK 32
#define THREADS 256
#define NCHUNK (DDIM / BK)     // 16
#define LDA 40                 // halves per A smem row (32 + 8 pad)
#define LDB 136                // halves per B smem row (128 + 8 pad)

// Scratch (allocation APIs forbidden; __device__ globals are the sanctioned path)
__device__ float g_mid[(size_t)BATCH * IN_SIZE];
__device__ float g_beff1[IN_SIZE];
__device__ float g_beff2[IN_SIZE];

// ---------------------------------------------------------------------------
// bias_eff[c] = bias[c] + nb * sum_k W[p][k][c]   (prologue folding)
// 8 threads per column, 64-element partial sums, shfl reduce.
__global__ void beff_kernel(const float* __restrict__ W,
                            const float* __restrict__ bias,
                            const float* __restrict__ nb,
                            float* __restrict__ beff) {
    int gid = blockIdx.x * blockDim.x + threadIdx.x;   // 0..32767
    int c = gid >> 3;
    int s = gid & 7;
    int p = c >> 9;
    int col = c & 511;
    const float* Wp = W + (size_t)p * DDIM * DDIM + col;
    float sum = 0.f;
    int k0 = s * 64;
    #pragma unroll 8
    for (int k = k0; k < k0 + 64; k++) sum += Wp[(size_t)k * DDIM];
    #pragma unroll
    for (int m = 4; m >= 1; m >>= 1) sum += __shfl_xor_sync(0xFFFFFFFFu, sum, m);
    if (s == 0) beff[c] = bias[c] + nb[0] * sum;
}

// ---------------------------------------------------------------------------
__device__ __forceinline__ uint32_t smem_u32(const void* p) {
    return (uint32_t)__cvta_generic_to_shared(p);
}

__device__ __forceinline__ void ldsm_x4(uint32_t& r0, uint32_t& r1, uint32_t& r2,
                                        uint32_t& r3, uint32_t addr) {
    asm volatile("ldmatrix.sync.aligned.m8n8.x4.shared.b16 {%0,%1,%2,%3}, [%4];"
                 : "=r"(r0), "=r"(r1), "=r"(r2), "=r"(r3) : "r"(addr));
}
__device__ __forceinline__ void ldsm_x4_t(uint32_t& r0, uint32_t& r1, uint32_t& r2,
                                          uint32_t& r3, uint32_t addr) {
    asm volatile("ldmatrix.sync.aligned.m8n8.x4.trans.shared.b16 {%0,%1,%2,%3}, [%4];"
                 : "=r"(r0), "=r"(r1), "=r"(r2), "=r"(r3) : "r"(addr));
}

__device__ __forceinline__ void mma_bf16(float c[4], const uint32_t a[4],
                                         uint32_t b0, uint32_t b1) {
    asm volatile(
        "mma.sync.aligned.m16n8k16.row.col.f32.bf16.bf16.f32 "
        "{%0,%1,%2,%3}, {%4,%5,%6,%7}, {%8,%9}, {%0,%1,%2,%3};"
        : "+f"(c[0]), "+f"(c[1]), "+f"(c[2]), "+f"(c[3])
        : "r"(a[0]), "r"(a[1]), "r"(a[2]), "r"(a[3]), "r"(b0), "r"(b1));
}

// ---------------------------------------------------------------------------
// One layer: Out = swish( gain*(A @ W_p) + bias_eff, gamma, beta ) [+ X residual]
template <bool SECOND>
__global__ __launch_bounds__(THREADS)
void bt_layer_kernel(const float* __restrict__ X,
                     const float* __restrict__ W,
                     const float* __restrict__ gamma,
                     const float* __restrict__ beta,
                     const float* __restrict__ gain_p,
                     float* __restrict__ Out) {
    const float* A    = SECOND ? g_mid : X;
    const float* beff = SECOND ? g_beff2 : g_beff1;
    float*       out  = SECOND ? Out : g_mid;

    const int tid  = threadIdx.x;
    const int warp = tid >> 5;
    const int lane = tid & 31;

    const int ng = blockIdx.x;           // 0..31  (partition*4 + n-tile)
    const int mt = blockIdx.y;           // 0..127 (M tiles)
    const int p  = ng >> 2;
    const int nt = ng & 3;

    const int row0  = mt * BM;
    const int colp0 = nt * BN;
    const int gcol0 = p * DDIM + colp0;

    const float gain = gain_p[0];

    __shared__ __nv_bfloat16 As[2][BM * LDA];
    __shared__ __nv_bfloat16 Bs[2][BK * LDB];

    // Warp layout: 4 (M) x 2 (N); warp tile 32x64
    const int wm = (warp >> 1) * 32;
    const int wn = (warp & 1) * 64;

    float acc[2][8][4];
    #pragma unroll
    for (int i = 0; i < 2; i++)
        #pragma unroll
        for (int j = 0; j < 8; j++)
            #pragma unroll
            for (int k = 0; k < 4; k++) acc[i][j][k] = 0.0f;

    const float* Ag = A + (size_t)row0 * IN_SIZE + p * DDIM;          // + k0 + ...
    const float* Bg = W + (size_t)p * DDIM * DDIM + colp0;            // + k0*DDIM + ...

    float4 ra[4], rb[4];

    // --- prologue: chunk 0
    #pragma unroll
    for (int i = 0; i < 4; i++) {
        int idx = tid + i * THREADS;
        ra[i] = *reinterpret_cast<const float4*>(Ag + (size_t)(idx >> 3) * IN_SIZE + ((idx & 7) << 2));
        rb[i] = *reinterpret_cast<const float4*>(Bg + (size_t)(idx >> 5) * DDIM + ((idx & 31) << 2));
    }
    #pragma unroll
    for (int i = 0; i < 4; i++) {
        int idx = tid + i * THREADS;
        {   // A
            int r = idx >> 3, c = (idx & 7) << 2;
            __nv_bfloat16* dst = &As[0][r * LDA + c];
            *reinterpret_cast<__nv_bfloat162*>(dst)     = __floats2bfloat162_rn(ra[i].x, ra[i].y);
            *reinterpret_cast<__nv_bfloat162*>(dst + 2) = __floats2bfloat162_rn(ra[i].z, ra[i].w);
        }
        {   // B
            int r = idx >> 5, c = (idx & 31) << 2;
            __nv_bfloat16* dst = &Bs[0][r * LDB + c];
            *reinterpret_cast<__nv_bfloat162*>(dst)     = __floats2bfloat162_rn(rb[i].x, rb[i].y);
            *reinterpret_cast<__nv_bfloat162*>(dst + 2) = __floats2bfloat162_rn(rb[i].z, rb[i].w);
        }
    }
    __syncthreads();

    // Per-buffer ldmatrix base addresses (byte offsets within smem)
    const int a_lrow = wm + (lane & 15);                // + im*16
    const int a_koff = (lane >> 4) << 3;                // + kk
    const int b_krow = (lane & 15);                     // + kk
    const int b_noff = wn + ((lane >> 4) << 3);         // + np*16

    int buf = 0;
    #pragma unroll 1
    for (int kc = 0; kc < NCHUNK; kc++) {
        // prefetch next chunk into registers
        if (kc + 1 < NCHUNK) {
            const int k0 = (kc + 1) * BK;
            #pragma unroll
            for (int i = 0; i < 4; i++) {
                int idx = tid + i * THREADS;
                ra[i] = *reinterpret_cast<const float4*>(
                    Ag + (size_t)(idx >> 3) * IN_SIZE + k0 + ((idx & 7) << 2));
                rb[i] = *reinterpret_cast<const float4*>(
                    Bg + (size_t)(k0 + (idx >> 5)) * DDIM + ((idx & 31) << 2));
            }
        }

        // compute current chunk
        const uint32_t a_base = smem_u32(&As[buf][0]);
        const uint32_t b_base = smem_u32(&Bs[buf][0]);
        #pragma unroll
        for (int kk = 0; kk < BK; kk += 16) {
            uint32_t af[2][4];
            #pragma unroll
            for (int im = 0; im < 2; im++) {
                uint32_t addr = a_base +
                    (((a_lrow + im * 16) * LDA) + kk + a_koff) * 2;
                ldsm_x4(af[im][0], af[im][1], af[im][2], af[im][3], addr);
            }
            #pragma unroll
            for (int np = 0; np < 4; np++) {
                uint32_t b0, b1, b2, b3;
                uint32_t addr = b_base +
                    (((kk + b_krow) * LDB) + b_noff + np * 16) * 2;
                ldsm_x4_t(b0, b1, b2, b3, addr);
                #pragma unroll
                for (int im = 0; im < 2; im++) {
                    mma_bf16(acc[im][np * 2 + 0], af[im], b0, b1);
                    mma_bf16(acc[im][np * 2 + 1], af[im], b2, b3);
                }
            }
        }

        // store next chunk into the other buffer
        if (kc + 1 < NCHUNK) {
            __nv_bfloat16* asn = &As[buf ^ 1][0];
            __nv_bfloat16* bsn = &Bs[buf ^ 1][0];
            #pragma unroll
            for (int i = 0; i < 4; i++) {
                int idx = tid + i * THREADS;
                {
                    int r = idx >> 3, c = (idx & 7) << 2;
                    __nv_bfloat16* dst = asn + r * LDA + c;
                    *reinterpret_cast<__nv_bfloat162*>(dst)     = __floats2bfloat162_rn(ra[i].x, ra[i].y);
                    *reinterpret_cast<__nv_bfloat162*>(dst + 2) = __floats2bfloat162_rn(ra[i].z, ra[i].w);
                }
                {
                    int r = idx >> 5, c = (idx & 31) << 2;
                    __nv_bfloat16* dst = bsn + r * LDB + c;
                    *reinterpret_cast<__nv_bfloat162*>(dst)     = __floats2bfloat162_rn(rb[i].x, rb[i].y);
                    *reinterpret_cast<__nv_bfloat162*>(dst + 2) = __floats2bfloat162_rn(rb[i].z, rb[i].w);
                }
            }
            __syncthreads();
            buf ^= 1;
        }
    }

    // --- epilogue: v = gain*acc + bias_eff; parametric swish; (+residual)
    const int g  = lane >> 2;
    const int t2 = (lane & 3) << 1;
    #pragma unroll
    for (int im = 0; im < 2; im++) {
        #pragma unroll
        for (int n_ = 0; n_ < 8; n_++) {
            const int rowA = row0 + wm + im * 16 + g;
            const int col  = gcol0 + wn + n_ * 8 + t2;
            const float be0 = beff[col],     be1 = beff[col + 1];
            const float gm0 = gamma[col],    gm1 = gamma[col + 1];
            const float bt0 = beta[col],     bt1 = beta[col + 1];
            #pragma unroll
            for (int h = 0; h < 2; h++) {
                const int rg = rowA + h * 8;
                float v0 = gain * acc[im][n_][h * 2 + 0] + be0;
                float v1 = gain * acc[im][n_][h * 2 + 1] + be1;
                const float s0 = 1.0f / (1.0f + __expf(-bt0 * v0));
                const float s1 = 1.0f / (1.0f + __expf(-bt1 * v1));
                float o0 = (gm0 + s0 * (1.0f - gm0)) * v0;
                float o1 = (gm1 + s1 * (1.0f - gm1)) * v1;
                if (SECOND) {
                    const float2 rx = *reinterpret_cast<const float2*>(
                        &X[(size_t)rg * IN_SIZE + col]);
                    o0 += rx.x;
                    o1 += rx.y;
                }
                float2 ov = make_float2(o0, o1);
                *reinterpret_cast<float2*>(&out[(size_t)rg * IN_SIZE + col]) = ov;
            }
        }
    }
}

// ---------------------------------------------------------------------------
extern "C" void kernel_launch(void* const* d_in, const int* in_sizes, int n_in,
                              void* d_out, int out_size) {
    (void)in_sizes; (void)n_in; (void)out_size;
    const float* x      = (const float*)d_in[0];
    const float* w1     = (const float*)d_in[1];
    const float* b1     = (const float*)d_in[2];
    const float* w2     = (const float*)d_in[3];
    const float* b2     = (const float*)d_in[4];
    const float* gamma1 = (const float*)d_in[5];
    const float* beta1  = (const float*)d_in[6];
    const float* gamma3 = (const float*)d_in[7];
    const float* beta3  = (const float*)d_in[8];
    const float* gain1  = (const float*)d_in[9];
    const float* nbias1 = (const float*)d_in[10];
    const float* gain3  = (const float*)d_in[11];
    const float* nbias3 = (const float*)d_in[12];
    float* out = (float*)d_out;

    float* beff1;
    float* beff2;
    cudaGetSymbolAddress((void**)&beff1, g_beff1);
    cudaGetSymbolAddress((void**)&beff2, g_beff2);

    // Fold the elementwise prologue into effective biases
    beff_kernel<<<128, 256>>>(w1, b1, nbias1, beff1);
    beff_kernel<<<128, 256>>>(w2, b2, nbias3, beff2);

    dim3 grid(32, 128);   // x = partition*4 + n-tile, y = m-tile (L2 A-reuse)
    dim3 block(THREADS);

    bt_layer_kernel<false><<<grid, block>>>(x, w1, gamma1, beta1, gain1, out);
    bt_layer_kernel<true ><<<grid, block>>>(x, w2, gamma3, beta3, gain3, out);
}

// round 4
// speedup vs baseline: 2.1357x; 2.1357x over previous
#include <cuda_runtime.h>
#include <cuda_bf16.h>
#include <cstdint>

#define BATCH   16384
#define IN_SIZE 4096
#define NPART   8
#define DDIM    512

#define BM 128
#define BN 128
#define BK 32
#define THREADS 256
#define NCHUNK (DDIM / BK)       // 16
#define STAGES 4
#define LDA 40                   // halves per A smem row (32 + 8 pad) = 80 B
#define LDB 136                  // halves per B smem row (128 + 8 pad) = 272 B
#define A_STAGE_BYTES (BM * LDA * 2)   // 10240
#define B_STAGE_BYTES (BK * LDB * 2)   // 8704
#define SMEM_TOTAL (STAGES * (A_STAGE_BYTES + B_STAGE_BYTES))  // 75776

// Device-global scratch (allocation APIs forbidden)
__device__ __align__(16) __nv_bfloat16 g_xb  [(size_t)BATCH * IN_SIZE];
__device__ __align__(16) __nv_bfloat16 g_midb[(size_t)BATCH * IN_SIZE];
__device__ __align__(16) __nv_bfloat16 g_w1b [(size_t)NPART * DDIM * DDIM];
__device__ __align__(16) __nv_bfloat16 g_w2b [(size_t)NPART * DDIM * DDIM];
__device__ float g_beff1[IN_SIZE];
__device__ float g_beff2[IN_SIZE];

// ---------------------------------------------------------------------------
#define CP_ASYNC_CG(dst, src) \
    asm volatile("cp.async.cg.shared.global [%0], [%1], 16;\n" :: "r"(dst), "l"(src))
#define CP_ASYNC_COMMIT() asm volatile("cp.async.commit_group;\n" ::: "memory")
#define CP_ASYNC_WAIT(n)  asm volatile("cp.async.wait_group %0;\n" :: "n"(n) : "memory")

__device__ __forceinline__ void ldsm_x4(uint32_t& r0, uint32_t& r1, uint32_t& r2,
                                        uint32_t& r3, uint32_t addr) {
    asm volatile("ldmatrix.sync.aligned.m8n8.x4.shared.b16 {%0,%1,%2,%3}, [%4];"
                 : "=r"(r0), "=r"(r1), "=r"(r2), "=r"(r3) : "r"(addr));
}
__device__ __forceinline__ void ldsm_x4_t(uint32_t& r0, uint32_t& r1, uint32_t& r2,
                                          uint32_t& r3, uint32_t addr) {
    asm volatile("ldmatrix.sync.aligned.m8n8.x4.trans.shared.b16 {%0,%1,%2,%3}, [%4];"
                 : "=r"(r0), "=r"(r1), "=r"(r2), "=r"(r3) : "r"(addr));
}
__device__ __forceinline__ void mma_bf16(float c[4], const uint32_t a[4],
                                         uint32_t b0, uint32_t b1) {
    asm volatile(
        "mma.sync.aligned.m16n8k16.row.col.f32.bf16.bf16.f32 "
        "{%0,%1,%2,%3}, {%4,%5,%6,%7}, {%8,%9}, {%0,%1,%2,%3};"
        : "+f"(c[0]), "+f"(c[1]), "+f"(c[2]), "+f"(c[3])
        : "r"(a[0]), "r"(a[1]), "r"(a[2]), "r"(a[3]), "r"(b0), "r"(b1));
}

// ---------------------------------------------------------------------------
// bias_eff[c] = bias[c] + nb * colsum(W)[c]
__global__ void beff_kernel(const float* __restrict__ W,
                            const float* __restrict__ bias,
                            const float* __restrict__ nb,
                            float* __restrict__ beff) {
    int gid = blockIdx.x * blockDim.x + threadIdx.x;
    int c = gid >> 3;
    int s = gid & 7;
    int p = c >> 9;
    int col = c & 511;
    const float* Wp = W + (size_t)p * DDIM * DDIM + col;
    float sum = 0.f;
    int k0 = s * 64;
    #pragma unroll 8
    for (int k = k0; k < k0 + 64; k++) sum += Wp[(size_t)k * DDIM];
    #pragma unroll
    for (int m = 4; m >= 1; m >>= 1) sum += __shfl_xor_sync(0xFFFFFFFFu, sum, m);
    if (s == 0) beff[c] = bias[c] + nb[0] * sum;
}

// W_eff = gain * W, converted to bf16 (4 elems/thread)
__global__ void convw_kernel(const float* __restrict__ W,
                             const float* __restrict__ gain_p,
                             __nv_bfloat16* __restrict__ Wb) {
    const float gain = gain_p[0];
    size_t i = ((size_t)blockIdx.x * blockDim.x + threadIdx.x) * 4;
    float4 v = *reinterpret_cast<const float4*>(W + i);
    __nv_bfloat162* dst = reinterpret_cast<__nv_bfloat162*>(Wb + i);
    dst[0] = __floats2bfloat162_rn(v.x * gain, v.y * gain);
    dst[1] = __floats2bfloat162_rn(v.z * gain, v.w * gain);
}

// x -> bf16 (8 elems/thread)
__global__ void convx_kernel(const float* __restrict__ X,
                             __nv_bfloat16* __restrict__ Xb) {
    size_t i = ((size_t)blockIdx.x * blockDim.x + threadIdx.x) * 8;
    float4 v0 = *reinterpret_cast<const float4*>(X + i);
    float4 v1 = *reinterpret_cast<const float4*>(X + i + 4);
    __nv_bfloat162 o[4];
    o[0] = __floats2bfloat162_rn(v0.x, v0.y);
    o[1] = __floats2bfloat162_rn(v0.z, v0.w);
    o[2] = __floats2bfloat162_rn(v1.x, v1.y);
    o[3] = __floats2bfloat162_rn(v1.z, v1.w);
    *reinterpret_cast<uint4*>(Xb + i) = *reinterpret_cast<uint4*>(o);
}

// ---------------------------------------------------------------------------
// One layer GEMM: Out = swish( A @ W_eff_p + beff, gamma, beta ) [+ X residual]
// SECOND=false: A = g_xb,   out -> g_midb (bf16)
// SECOND=true : A = g_midb, out -> Out (fp32) with +X residual
template <bool SECOND>
__global__ __launch_bounds__(THREADS, 2)
void bt_gemm(const float* __restrict__ X,
             const __nv_bfloat16* __restrict__ Ain,
             const __nv_bfloat16* __restrict__ Wb,
             const float* __restrict__ beff,
             const float* __restrict__ gamma,
             const float* __restrict__ beta,
             float* __restrict__ Out) {
    extern __shared__ char smem[];

    const int tid  = threadIdx.x;
    const int warp = tid >> 5;
    const int lane = tid & 31;

    const int ng = blockIdx.x;            // 0..31  (partition*4 + n-tile)
    const int mt = blockIdx.y;            // 0..127
    const int p  = ng >> 2;
    const int nt = ng & 3;

    const int row0  = mt * BM;
    const int colp0 = nt * BN;
    const int gcol0 = p * DDIM + colp0;

    const __nv_bfloat16* Ag = Ain + (size_t)row0 * IN_SIZE + p * DDIM;
    const __nv_bfloat16* Bg = Wb + (size_t)p * DDIM * DDIM + colp0;

    const uint32_t smem_base = (uint32_t)__cvta_generic_to_shared(smem);
    const uint32_t a_base0 = smem_base;
    const uint32_t b_base0 = smem_base + STAGES * A_STAGE_BYTES;

    // cp.async per-thread mapping (2 A chunks + 2 B chunks of 16 B each)
    const int a_row = tid >> 2;                 // 0..63 (+64 for 2nd)
    const int a_c   = (tid & 3) * 8;            // bf16 elem offset in row
    const int b_row = tid >> 4;                 // 0..15 (+16 for 2nd)
    const int b_c   = (tid & 15) * 8;

    const uint32_t a_dst_off = (uint32_t)(a_row * (LDA * 2) + a_c * 2);
    const uint32_t b_dst_off = (uint32_t)(b_row * (LDB * 2) + b_c * 2);

    // Warp layout: 4 (M) x 2 (N); warp tile 32x64
    const int wm = (warp >> 1) * 32;
    const int wn = (warp & 1) * 64;

    const int a_lrow = wm + (lane & 15);
    const int a_koff = (lane >> 4) << 3;
    const int b_krow = (lane & 15);
    const int b_noff = wn + ((lane >> 4) << 3);

    float acc[2][8][4];
    #pragma unroll
    for (int i = 0; i < 2; i++)
        #pragma unroll
        for (int j = 0; j < 8; j++)
            #pragma unroll
            for (int k = 0; k < 4; k++) acc[i][j][k] = 0.0f;

    // ---- issue a stage's copies
    auto issue = [&](int s, int k0) {
        uint32_t ad = a_base0 + s * A_STAGE_BYTES + a_dst_off;
        const __nv_bfloat16* as = Ag + (size_t)a_row * IN_SIZE + k0 + a_c;
        CP_ASYNC_CG(ad, as);
        CP_ASYNC_CG(ad + 64 * (LDA * 2), as + (size_t)64 * IN_SIZE);
        uint32_t bd = b_base0 + s * B_STAGE_BYTES + b_dst_off;
        const __nv_bfloat16* bs = Bg + (size_t)(k0 + b_row) * DDIM + b_c;
        CP_ASYNC_CG(bd, bs);
        CP_ASYNC_CG(bd + 16 * (LDB * 2), bs + (size_t)16 * DDIM);
    };

    // ---- prologue: fill STAGES-1 stages
    #pragma unroll
    for (int s = 0; s < STAGES - 1; s++) {
        issue(s, s * BK);
        CP_ASYNC_COMMIT();
    }

    int buf = 0;
    #pragma unroll 1
    for (int kc = 0; kc < NCHUNK; kc++) {
        CP_ASYNC_WAIT(STAGES - 2);
        __syncthreads();

        const uint32_t a_base = a_base0 + buf * A_STAGE_BYTES;
        const uint32_t b_base = b_base0 + buf * B_STAGE_BYTES;
        #pragma unroll
        for (int kk = 0; kk < BK; kk += 16) {
            uint32_t af[2][4];
            #pragma unroll
            for (int im = 0; im < 2; im++) {
                uint32_t addr = a_base + (((a_lrow + im * 16) * LDA) + kk + a_koff) * 2;
                ldsm_x4(af[im][0], af[im][1], af[im][2], af[im][3], addr);
            }
            #pragma unroll
            for (int np = 0; np < 4; np++) {
                uint32_t b0, b1, b2, b3;
                uint32_t addr = b_base + (((kk + b_krow) * LDB) + b_noff + np * 16) * 2;
                ldsm_x4_t(b0, b1, b2, b3, addr);
                #pragma unroll
                for (int im = 0; im < 2; im++) {
                    mma_bf16(acc[im][np * 2 + 0], af[im], b0, b1);
                    mma_bf16(acc[im][np * 2 + 1], af[im], b2, b3);
                }
            }
        }

        const int knext = kc + STAGES - 1;
        if (knext < NCHUNK) {
            issue(knext & (STAGES - 1), knext * BK);
        }
        CP_ASYNC_COMMIT();
        buf = (buf + 1) & (STAGES - 1);
    }

    // ---- epilogue: v = acc + beff; parametric swish; (+residual)
    const int g  = lane >> 2;
    const int t2 = (lane & 3) << 1;
    #pragma unroll
    for (int im = 0; im < 2; im++) {
        #pragma unroll
        for (int n_ = 0; n_ < 8; n_++) {
            const int rowA = row0 + wm + im * 16 + g;
            const int col  = gcol0 + wn + n_ * 8 + t2;
            const float be0 = beff[col],  be1 = beff[col + 1];
            const float gm0 = gamma[col], gm1 = gamma[col + 1];
            const float bt0 = beta[col],  bt1 = beta[col + 1];
            #pragma unroll
            for (int h = 0; h < 2; h++) {
                const int rg = rowA + h * 8;
                float v0 = acc[im][n_][h * 2 + 0] + be0;
                float v1 = acc[im][n_][h * 2 + 1] + be1;
                const float s0 = 1.0f / (1.0f + __expf(-bt0 * v0));
                const float s1 = 1.0f / (1.0f + __expf(-bt1 * v1));
                float o0 = (gm0 + s0 * (1.0f - gm0)) * v0;
                float o1 = (gm1 + s1 * (1.0f - gm1)) * v1;
                if (SECOND) {
                    const float2 rx = *reinterpret_cast<const float2*>(
                        &X[(size_t)rg * IN_SIZE + col]);
                    *reinterpret_cast<float2*>(&Out[(size_t)rg * IN_SIZE + col]) =
                        make_float2(o0 + rx.x, o1 + rx.y);
                } else {
                    *reinterpret_cast<__nv_bfloat162*>(
                        &g_midb[(size_t)rg * IN_SIZE + col]) =
                        __floats2bfloat162_rn(o0, o1);
                }
            }
        }
    }
}

// ---------------------------------------------------------------------------
extern "C" void kernel_launch(void* const* d_in, const int* in_sizes, int n_in,
                              void* d_out, int out_size) {
    (void)in_sizes; (void)n_in; (void)out_size;
    const float* x      = (const float*)d_in[0];
    const float* w1     = (const float*)d_in[1];
    const float* b1     = (const float*)d_in[2];
    const float* w2     = (const float*)d_in[3];
    const float* b2     = (const float*)d_in[4];
    const float* gamma1 = (const float*)d_in[5];
    const float* beta1  = (const float*)d_in[6];
    const float* gamma3 = (const float*)d_in[7];
    const float* beta3  = (const float*)d_in[8];
    const float* gain1  = (const float*)d_in[9];
    const float* nbias1 = (const float*)d_in[10];
    const float* gain3  = (const float*)d_in[11];
    const float* nbias3 = (const float*)d_in[12];
    float* out = (float*)d_out;

    __nv_bfloat16 *xb, *midb, *w1b, *w2b;
    float *beff1, *beff2;
    cudaGetSymbolAddress((void**)&xb,    g_xb);
    cudaGetSymbolAddress((void**)&midb,  g_midb);
    cudaGetSymbolAddress((void**)&w1b,   g_w1b);
    cudaGetSymbolAddress((void**)&w2b,   g_w2b);
    cudaGetSymbolAddress((void**)&beff1, g_beff1);
    cudaGetSymbolAddress((void**)&beff2, g_beff2);

    static bool attr_set = false;
    if (!attr_set) {
        cudaFuncSetAttribute(bt_gemm<false>,
                             cudaFuncAttributeMaxDynamicSharedMemorySize, SMEM_TOTAL);
        cudaFuncSetAttribute(bt_gemm<true>,
                             cudaFuncAttributeMaxDynamicSharedMemorySize, SMEM_TOTAL);
        attr_set = true;
    }

    // Preprocess: fold gain into bf16 weights, fold nbias into effective bias,
    // convert x to bf16.
    convw_kernel<<<(NPART * DDIM * DDIM) / (256 * 4), 256>>>(w1, gain1, w1b);
    convw_kernel<<<(NPART * DDIM * DDIM) / (256 * 4), 256>>>(w2, gain3, w2b);
    convx_kernel<<<(int)(((size_t)BATCH * IN_SIZE) / (256 * 8)), 256>>>(x, xb);
    beff_kernel<<<128, 256>>>(w1, b1, nbias1, beff1);
    beff_kernel<<<128, 256>>>(w2, b2, nbias3, beff2);

    dim3 grid(32, 128);
    dim3 block(THREADS);

    bt_gemm<false><<<grid, block, SMEM_TOTAL>>>(x, xb,   w1b, beff1, gamma1, beta1, out);
    bt_gemm<true ><<<grid, block, SMEM_TOTAL>>>(x, midb, w2b, beff2, gamma3, beta3, out);
}

// round 6
// speedup vs baseline: 2.2173x; 1.0382x over previous
#include <cuda_runtime.h>
#include <cuda_bf16.h>
#include <cstdint>

#define BATCH   16384
#define IN_SIZE 4096
#define NPART   8
#define DDIM    512

#define BM 128
#define BN 128
#define BK 64
#define THREADS 256
#define NCHUNK (DDIM / BK)       // 8
#define STAGES 3
#define LDA 72                   // halves per A smem row (64 + 8 pad) = 144 B
#define LDB 136                  // halves per B smem row (128 + 8 pad) = 272 B
#define A_STAGE_BYTES (BM * LDA * 2)   // 18432
#define B_STAGE_BYTES (BK * LDB * 2)   // 17408
#define SMEM_TOTAL (STAGES * (A_STAGE_BYTES + B_STAGE_BYTES))  // 107520

// Device-global scratch (allocation APIs forbidden)
__device__ __align__(16) __nv_bfloat16 g_xb  [(size_t)BATCH * IN_SIZE];
__device__ __align__(16) __nv_bfloat16 g_midb[(size_t)BATCH * IN_SIZE];
__device__ __align__(16) __nv_bfloat16 g_w1b [(size_t)NPART * DDIM * DDIM];
__device__ __align__(16) __nv_bfloat16 g_w2b [(size_t)NPART * DDIM * DDIM];
__device__ float g_beff1[IN_SIZE];
__device__ float g_beff2[IN_SIZE];

// ---------------------------------------------------------------------------
#define CP_ASYNC_CG(dst, src) \
    asm volatile("cp.async.cg.shared.global [%0], [%1], 16;\n" :: "r"(dst), "l"(src))
#define CP_ASYNC_COMMIT() asm volatile("cp.async.commit_group;\n" ::: "memory")
#define CP_ASYNC_WAIT(n)  asm volatile("cp.async.wait_group %0;\n" :: "n"(n) : "memory")

__device__ __forceinline__ void ldsm_x4(uint32_t& r0, uint32_t& r1, uint32_t& r2,
                                        uint32_t& r3, uint32_t addr) {
    asm volatile("ldmatrix.sync.aligned.m8n8.x4.shared.b16 {%0,%1,%2,%3}, [%4];"
                 : "=r"(r0), "=r"(r1), "=r"(r2), "=r"(r3) : "r"(addr));
}
__device__ __forceinline__ void ldsm_x4_t(uint32_t& r0, uint32_t& r1, uint32_t& r2,
                                          uint32_t& r3, uint32_t addr) {
    asm volatile("ldmatrix.sync.aligned.m8n8.x4.trans.shared.b16 {%0,%1,%2,%3}, [%4];"
                 : "=r"(r0), "=r"(r1), "=r"(r2), "=r"(r3) : "r"(addr));
}
__device__ __forceinline__ void mma_bf16(float c[4], const uint32_t a[4],
                                         uint32_t b0, uint32_t b1) {
    asm volatile(
        "mma.sync.aligned.m16n8k16.row.col.f32.bf16.bf16.f32 "
        "{%0,%1,%2,%3}, {%4,%5,%6,%7}, {%8,%9}, {%0,%1,%2,%3};"
        : "+f"(c[0]), "+f"(c[1]), "+f"(c[2]), "+f"(c[3])
        : "r"(a[0]), "r"(a[1]), "r"(a[2]), "r"(a[3]), "r"(b0), "r"(b1));
}

// ---------------------------------------------------------------------------
// bias_eff[c] = bias[c] + nb * colsum(W)[c]
__global__ void beff_kernel(const float* __restrict__ W,
                            const float* __restrict__ bias,
                            const float* __restrict__ nb,
                            float* __restrict__ beff) {
    int gid = blockIdx.x * blockDim.x + threadIdx.x;
    int c = gid >> 3;
    int s = gid & 7;
    int p = c >> 9;
    int col = c & 511;
    const float* Wp = W + (size_t)p * DDIM * DDIM + col;
    float sum = 0.f;
    int k0 = s * 64;
    #pragma unroll 8
    for (int k = k0; k < k0 + 64; k++) sum += Wp[(size_t)k * DDIM];
    #pragma unroll
    for (int m = 4; m >= 1; m >>= 1) sum += __shfl_xor_sync(0xFFFFFFFFu, sum, m);
    if (s == 0) beff[c] = bias[c] + nb[0] * sum;
}

// W_eff = gain * W, converted to bf16 (4 elems/thread)
__global__ void convw_kernel(const float* __restrict__ W,
                             const float* __restrict__ gain_p,
                             __nv_bfloat16* __restrict__ Wb) {
    const float gain = gain_p[0];
    size_t i = ((size_t)blockIdx.x * blockDim.x + threadIdx.x) * 4;
    float4 v = *reinterpret_cast<const float4*>(W + i);
    __nv_bfloat162* dst = reinterpret_cast<__nv_bfloat162*>(Wb + i);
    dst[0] = __floats2bfloat162_rn(v.x * gain, v.y * gain);
    dst[1] = __floats2bfloat162_rn(v.z * gain, v.w * gain);
}

// x -> bf16 (8 elems/thread)
__global__ void convx_kernel(const float* __restrict__ X,
                             __nv_bfloat16* __restrict__ Xb) {
    size_t i = ((size_t)blockIdx.x * blockDim.x + threadIdx.x) * 8;
    float4 v0 = *reinterpret_cast<const float4*>(X + i);
    float4 v1 = *reinterpret_cast<const float4*>(X + i + 4);
    __nv_bfloat162 o[4];
    o[0] = __floats2bfloat162_rn(v0.x, v0.y);
    o[1] = __floats2bfloat162_rn(v0.z, v0.w);
    o[2] = __floats2bfloat162_rn(v1.x, v1.y);
    o[3] = __floats2bfloat162_rn(v1.z, v1.w);
    *reinterpret_cast<uint4*>(Xb + i) = *reinterpret_cast<uint4*>(o);
}

// ---------------------------------------------------------------------------
// One layer GEMM: Out = swish( A @ W_eff_p + beff, gamma, beta ) [+ X residual]
template <bool SECOND>
__global__ __launch_bounds__(THREADS, 2)
void bt_gemm(const float* __restrict__ X,
             const __nv_bfloat16* __restrict__ Ain,
             const __nv_bfloat16* __restrict__ Wb,
             const float* __restrict__ beff,
             const float* __restrict__ gamma,
             const float* __restrict__ beta,
             float* __restrict__ Out,
             __nv_bfloat16* __restrict__ MidOut) {
    extern __shared__ char smem[];

    const int tid  = threadIdx.x;
    const int warp = tid >> 5;
    const int lane = tid & 31;

    const int ng = blockIdx.x;            // 0..31  (partition*4 + n-tile)
    const int mt = blockIdx.y;            // 0..127
    const int p  = ng >> 2;
    const int nt = ng & 3;

    const int row0  = mt * BM;
    const int colp0 = nt * BN;
    const int gcol0 = p * DDIM + colp0;

    const __nv_bfloat16* Ag = Ain + (size_t)row0 * IN_SIZE + p * DDIM;
    const __nv_bfloat16* Bg = Wb + (size_t)p * DDIM * DDIM + colp0;

    const uint32_t smem_base = (uint32_t)__cvta_generic_to_shared(smem);
    const uint32_t a_base0 = smem_base;
    const uint32_t b_base0 = smem_base + STAGES * A_STAGE_BYTES;

    // cp.async per-thread mapping: 4 A + 4 B 16-byte copies per stage
    const int a_row = tid >> 3;                 // base row 0..31 (x4 via idx)
    // (computed per-iteration below from idx)

    // Warp layout: 4 (M) x 2 (N); warp tile 32x64
    const int wm = (warp >> 1) * 32;
    const int wn = (warp & 1) * 64;

    const int a_lrow = wm + (lane & 15);
    const int a_koff = (lane >> 4) << 3;
    const int b_krow = (lane & 15);
    const int b_noff = wn + ((lane >> 4) << 3);

    float acc[2][8][4];
    #pragma unroll
    for (int i = 0; i < 2; i++)
        #pragma unroll
        for (int j = 0; j < 8; j++)
            #pragma unroll
            for (int k = 0; k < 4; k++) acc[i][j][k] = 0.0f;

    // ---- issue one stage: A 128x64 bf16, B 64x128 bf16
    auto issue = [&](int s, int k0) {
        const uint32_t a_st = a_base0 + s * A_STAGE_BYTES;
        #pragma unroll
        for (int i = 0; i < 4; i++) {
            int idx = tid + i * THREADS;          // 0..1023
            int r = idx >> 3, c16 = idx & 7;      // r: 0..127, c16: 0..7
            uint32_t dst = a_st + (uint32_t)(r * (LDA * 2) + c16 * 16);
            CP_ASYNC_CG(dst, Ag + (size_t)r * IN_SIZE + k0 + (c16 << 3));
        }
        const uint32_t b_st = b_base0 + s * B_STAGE_BYTES;
        #pragma unroll
        for (int i = 0; i < 4; i++) {
            int idx = tid + i * THREADS;          // 0..1023
            int r = idx >> 4, c16 = idx & 15;     // r: 0..63, c16: 0..15
            uint32_t dst = b_st + (uint32_t)(r * (LDB * 2) + c16 * 16);
            CP_ASYNC_CG(dst, Bg + (size_t)(k0 + r) * DDIM + (c16 << 3));
        }
        CP_ASYNC_COMMIT();
    };
    (void)a_row;

    // ---- prologue: 2 stages in flight
    issue(0, 0);
    issue(1, BK);

    #pragma unroll
    for (int kc = 0; kc < NCHUNK; kc++) {
        const int s = kc % STAGES;
        if (kc < NCHUNK - 1) { CP_ASYNC_WAIT(1); }
        else                 { CP_ASYNC_WAIT(0); }
        __syncthreads();

        // issue stage kc+2 NOW so it overlaps this chunk's compute
        // (stage being overwritten was consumed in chunk kc-1; the sync above
        //  guarantees all threads are done with it)
        if (kc + 2 < NCHUNK) issue((kc + 2) % STAGES, (kc + 2) * BK);

        const uint32_t a_base = a_base0 + s * A_STAGE_BYTES;
        const uint32_t b_base = b_base0 + s * B_STAGE_BYTES;
        #pragma unroll
        for (int kk = 0; kk < BK; kk += 16) {
            uint32_t af[2][4];
            #pragma unroll
            for (int im = 0; im < 2; im++) {
                uint32_t addr = a_base + (((a_lrow + im * 16) * LDA) + kk + a_koff) * 2;
                ldsm_x4(af[im][0], af[im][1], af[im][2], af[im][3], addr);
            }
            #pragma unroll
            for (int np = 0; np < 4; np++) {
                uint32_t b0, b1, b2, b3;
                uint32_t addr = b_base + (((kk + b_krow) * LDB) + b_noff + np * 16) * 2;
                ldsm_x4_t(b0, b1, b2, b3, addr);
                #pragma unroll
                for (int im = 0; im < 2; im++) {
                    mma_bf16(acc[im][np * 2 + 0], af[im], b0, b1);
                    mma_bf16(acc[im][np * 2 + 1], af[im], b2, b3);
                }
            }
        }
    }

    // ---- epilogue: v = acc + beff; parametric swish; (+residual)
    const int g  = lane >> 2;
    const int t2 = (lane & 3) << 1;
    #pragma unroll
    for (int im = 0; im < 2; im++) {
        #pragma unroll
        for (int n_ = 0; n_ < 8; n_++) {
            const int rowA = row0 + wm + im * 16 + g;
            const int col  = gcol0 + wn + n_ * 8 + t2;
            const float be0 = beff[col],  be1 = beff[col + 1];
            const float gm0 = gamma[col], gm1 = gamma[col + 1];
            const float bt0 = beta[col],  bt1 = beta[col + 1];
            #pragma unroll
            for (int h = 0; h < 2; h++) {
                const int rg = rowA + h * 8;
                float v0 = acc[im][n_][h * 2 + 0] + be0;
                float v1 = acc[im][n_][h * 2 + 1] + be1;
                const float s0 = 1.0f / (1.0f + __expf(-bt0 * v0));
                const float s1 = 1.0f / (1.0f + __expf(-bt1 * v1));
                float o0 = (gm0 + s0 * (1.0f - gm0)) * v0;
                float o1 = (gm1 + s1 * (1.0f - gm1)) * v1;
                if (SECOND) {
                    const float2 rx = *reinterpret_cast<const float2*>(
                        &X[(size_t)rg * IN_SIZE + col]);
                    *reinterpret_cast<float2*>(&Out[(size_t)rg * IN_SIZE + col]) =
                        make_float2(o0 + rx.x, o1 + rx.y);
                } else {
                    *reinterpret_cast<__nv_bfloat162*>(
                        &MidOut[(size_t)rg * IN_SIZE + col]) =
                        __floats2bfloat162_rn(o0, o1);
                }
            }
        }
    }
}

// ---------------------------------------------------------------------------
extern "C" void kernel_launch(void* const* d_in, const int* in_sizes, int n_in,
                              void* d_out, int out_size) {
    (void)in_sizes; (void)n_in; (void)out_size;
    const float* x      = (const float*)d_in[0];
    const float* w1     = (const float*)d_in[1];
    const float* b1     = (const float*)d_in[2];
    const float* w2     = (const float*)d_in[3];
    const float* b2     = (const float*)d_in[4];
    const float* gamma1 = (const float*)d_in[5];
    const float* beta1  = (const float*)d_in[6];
    const float* gamma3 = (const float*)d_in[7];
    const float* beta3  = (const float*)d_in[8];
    const float* gain1  = (const float*)d_in[9];
    const float* nbias1 = (const float*)d_in[10];
    const float* gain3  = (const float*)d_in[11];
    const float* nbias3 = (const float*)d_in[12];
    float* out = (float*)d_out;

    __nv_bfloat16 *xb, *midb, *w1b, *w2b;
    float *beff1, *beff2;
    cudaGetSymbolAddress((void**)&xb,    g_xb);
    cudaGetSymbolAddress((void**)&midb,  g_midb);
    cudaGetSymbolAddress((void**)&w1b,   g_w1b);
    cudaGetSymbolAddress((void**)&w2b,   g_w2b);
    cudaGetSymbolAddress((void**)&beff1, g_beff1);
    cudaGetSymbolAddress((void**)&beff2, g_beff2);

    cudaFuncSetAttribute(bt_gemm<false>,
                         cudaFuncAttributeMaxDynamicSharedMemorySize, SMEM_TOTAL);
    cudaFuncSetAttribute(bt_gemm<true>,
                         cudaFuncAttributeMaxDynamicSharedMemorySize, SMEM_TOTAL);

    // Preprocess: fold gain into bf16 weights, fold nbias into effective bias,
    // convert x to bf16.
    convw_kernel<<<(NPART * DDIM * DDIM) / (256 * 4), 256>>>(w1, gain1, w1b);
    convw_kernel<<<(NPART * DDIM * DDIM) / (256 * 4), 256>>>(w2, gain3, w2b);
    convx_kernel<<<(int)(((size_t)BATCH * IN_SIZE) / (256 * 8)), 256>>>(x, xb);
    beff_kernel<<<128, 256>>>(w1, b1, nbias1, beff1);
    beff_kernel<<<128, 256>>>(w2, b2, nbias3, beff2);

    dim3 grid(32, 128);
    dim3 block(THREADS);

    bt_gemm<false><<<grid, block, SMEM_TOTAL>>>(x, xb,   w1b, beff1, gamma1, beta1, out, midb);
    bt_gemm<true ><<<grid, block, SMEM_TOTAL>>>(x, midb, w2b, beff2, gamma3, beta3, out, midb);
}

// round 7
// speedup vs baseline: 2.3600x; 1.0644x over previous
#include <cuda_runtime.h>
#include <cuda_bf16.h>
#include <cstdint>

#define BATCH   16384
#define IN_SIZE 4096
#define NPART   8
#define DDIM    512

#define BM 128
#define BN 128
#define BK 64
#define THREADS 256
#define NCHUNK (DDIM / BK)       // 8
#define STAGES 3

#define TILE_BYTES   16384       // one 16KB operand tile (A: 128x64 bf16, B: 64x128 bf16)
#define STAGE_BYTES  (2 * TILE_BYTES)
#define SMEM_STAGE0  1024
#define SMEM_TOTAL   (SMEM_STAGE0 + STAGES * STAGE_BYTES)   // 99328

// Device-global scratch (allocation APIs forbidden).
// xb/midb: tile-major swizzled bf16 activations. tile index = (mt*8+p)*8+kc
// w1b/w2b: tile-major swizzled bf16 weights.     tile index = (p*4+nt)*8+kc
__device__ __align__(16) __nv_bfloat16 g_xb  [(size_t)BATCH * IN_SIZE];
__device__ __align__(16) __nv_bfloat16 g_midb[(size_t)BATCH * IN_SIZE];
__device__ __align__(16) __nv_bfloat16 g_w1b [(size_t)NPART * DDIM * DDIM];
__device__ __align__(16) __nv_bfloat16 g_w2b [(size_t)NPART * DDIM * DDIM];
__device__ float g_beff1[IN_SIZE];
__device__ float g_beff2[IN_SIZE];

// ---------------------------------------------------------------------------
#define MBARRIER_INIT(addr, cnt) \
    asm volatile("mbarrier.init.shared.b64 [%0], %1;" :: "r"(addr), "r"(cnt) : "memory")
#define MBARRIER_EXPECT_TX(addr, bytes) \
    asm volatile("mbarrier.arrive.expect_tx.shared.b64 _, [%0], %1;" \
                 :: "r"(addr), "r"(bytes) : "memory")
#define MBARRIER_WAIT_PARITY(mbar, par) do {                                   \
    uint32_t _m = (mbar); uint32_t _p = (par); uint32_t _done;                 \
    asm volatile("{\n\t.reg .pred p;\n\t"                                      \
        "mbarrier.try_wait.parity.acquire.cta.shared::cta.b64 p, [%1], %2;\n\t"\
        "selp.b32 %0, 1, 0, p;\n\t}"                                           \
        : "=r"(_done) : "r"(_m), "r"(_p) : "memory");                          \
    if (!_done) {                                                              \
        asm volatile("{\n\t.reg .pred P1;\n\t"                                 \
            "WAIT_LOOP_%=:\n\t"                                                \
            "mbarrier.try_wait.parity.acquire.cta.shared::cta.b64 P1, [%0], %1, 0x989680;\n\t" \
            "@P1 bra.uni WAIT_DONE_%=;\n\t"                                    \
            "bra.uni WAIT_LOOP_%=;\n\t"                                        \
            "WAIT_DONE_%=:\n\t}"                                               \
            :: "r"(_m), "r"(_p) : "memory");                                   \
    }                                                                          \
} while (0)

// Bulk async copy global->shared (UBLKCP). sm_90 baseline PTX (not 'a'-gated).
#define CP_BULK_G2S(dst, src, bytes, mbar) \
    asm volatile("cp.async.bulk.shared::cluster.global.mbarrier::complete_tx::bytes " \
                 "[%0], [%1], %2, [%3];" \
                 :: "r"(dst), "l"(src), "r"(bytes), "r"(mbar) : "memory")

__device__ __forceinline__ void ldsm_x4(uint32_t& r0, uint32_t& r1, uint32_t& r2,
                                        uint32_t& r3, uint32_t addr) {
    asm volatile("ldmatrix.sync.aligned.m8n8.x4.shared.b16 {%0,%1,%2,%3}, [%4];"
                 : "=r"(r0), "=r"(r1), "=r"(r2), "=r"(r3) : "r"(addr));
}
__device__ __forceinline__ void ldsm_x4_t(uint32_t& r0, uint32_t& r1, uint32_t& r2,
                                          uint32_t& r3, uint32_t addr) {
    asm volatile("ldmatrix.sync.aligned.m8n8.x4.trans.shared.b16 {%0,%1,%2,%3}, [%4];"
                 : "=r"(r0), "=r"(r1), "=r"(r2), "=r"(r3) : "r"(addr));
}
__device__ __forceinline__ void mma_bf16(float c[4], const uint32_t a[4],
                                         uint32_t b0, uint32_t b1) {
    asm volatile(
        "mma.sync.aligned.m16n8k16.row.col.f32.bf16.bf16.f32 "
        "{%0,%1,%2,%3}, {%4,%5,%6,%7}, {%8,%9}, {%0,%1,%2,%3};"
        : "+f"(c[0]), "+f"(c[1]), "+f"(c[2]), "+f"(c[3])
        : "r"(a[0]), "r"(a[1]), "r"(a[2]), "r"(a[3]), "r"(b0), "r"(b1));
}

// SW128 XOR swizzle over 128-byte rows (bits [6:4] ^= bits [9:7])
__device__ __forceinline__ uint32_t sw128(uint32_t off) {
    return off ^ ((off >> 3) & 0x70);
}

// ---------------------------------------------------------------------------
// bias_eff[c] = bias[c] + nb * colsum(W)[c]
__global__ void beff_kernel(const float* __restrict__ W,
                            const float* __restrict__ bias,
                            const float* __restrict__ nb,
                            float* __restrict__ beff) {
    int gid = blockIdx.x * blockDim.x + threadIdx.x;
    int c = gid >> 3;
    int s = gid & 7;
    int p = c >> 9;
    int col = c & 511;
    const float* Wp = W + (size_t)p * DDIM * DDIM + col;
    float sum = 0.f;
    int k0 = s * 64;
    #pragma unroll 8
    for (int k = k0; k < k0 + 64; k++) sum += Wp[(size_t)k * DDIM];
    #pragma unroll
    for (int m = 4; m >= 1; m >>= 1) sum += __shfl_xor_sync(0xFFFFFFFFu, sum, m);
    if (s == 0) beff[c] = bias[c] + nb[0] * sum;
}

// W * gain -> bf16, tiled+swizzled. B tile for (p,nt,kc): 64 K-rows x 128 N-cols,
// stored as two 64x64 halves; off = h*8192 + kk*128 + sw( nn*2 ^ swz(kk) ).
__global__ void convw_kernel(const float* __restrict__ W,
                             const float* __restrict__ gain_p,
                             __nv_bfloat16* __restrict__ Wb) {
    const float gain = gain_p[0];
    int gid = blockIdx.x * blockDim.x + threadIdx.x;   // 0..262143, 8 elems each
    int n0  = (gid & 63) * 8;        // 0..504 within partition (8-aligned)
    int k   = (gid >> 6) & 511;
    int p   = gid >> 15;

    const float* src = W + ((size_t)p * DDIM + k) * DDIM + n0;
    float4 v0 = *reinterpret_cast<const float4*>(src);
    float4 v1 = *reinterpret_cast<const float4*>(src + 4);
    __nv_bfloat162 o[4];
    o[0] = __floats2bfloat162_rn(v0.x * gain, v0.y * gain);
    o[1] = __floats2bfloat162_rn(v0.z * gain, v0.w * gain);
    o[2] = __floats2bfloat162_rn(v1.x * gain, v1.y * gain);
    o[3] = __floats2bfloat162_rn(v1.z * gain, v1.w * gain);

    int kc = k >> 6, kk = k & 63;
    int nt = n0 >> 7, h = (n0 >> 6) & 1, nn = n0 & 63;
    size_t tile = ((size_t)(p * 4 + nt) * NCHUNK + kc) * TILE_BYTES;
    uint32_t off = h * 8192 + kk * 128 + (uint32_t)((nn * 2) ^ ((kk & 7) * 16));
    *reinterpret_cast<uint4*>(reinterpret_cast<char*>(Wb) + tile + off) =
        *reinterpret_cast<uint4*>(o);
}

// x -> bf16, tiled+swizzled. A tile for (mt,p,kc): 128 rows x 64 K-cols;
// off = r*128 + sw(c*2).
__global__ void convx_kernel(const float* __restrict__ X,
                             __nv_bfloat16* __restrict__ Xb) {
    int gid = blockIdx.x * blockDim.x + threadIdx.x;   // 8.4M threads, 8 elems each
    int c0  = (gid & 63) * 8;        // col within row, 8-aligned (512 per (row,p))
    int prow = gid >> 6;             // row * 8 + p? No: decompose as (row, p, c)
    int p   = prow & 7;
    int row = prow >> 3;

    const float* src = X + (size_t)row * IN_SIZE + p * DDIM + c0;
    float4 v0 = *reinterpret_cast<const float4*>(src);
    float4 v1 = *reinterpret_cast<const float4*>(src + 4);
    __nv_bfloat162 o[4];
    o[0] = __floats2bfloat162_rn(v0.x, v0.y);
    o[1] = __floats2bfloat162_rn(v0.z, v0.w);
    o[2] = __floats2bfloat162_rn(v1.x, v1.y);
    o[3] = __floats2bfloat162_rn(v1.z, v1.w);

    int mt = row >> 7, r = row & 127;
    int kc = c0 >> 6, c = c0 & 63;
    size_t tile = ((size_t)(mt * NPART + p) * NCHUNK + kc) * TILE_BYTES;
    uint32_t off = r * 128 + (uint32_t)((c * 2) ^ ((r & 7) * 16));
    *reinterpret_cast<uint4*>(reinterpret_cast<char*>(Xb) + tile + off) =
        *reinterpret_cast<uint4*>(o);
}

// ---------------------------------------------------------------------------
// One layer GEMM: Out = swish( A @ W_eff_p + beff, gamma, beta ) [+ X residual]
// A (bf16) arrives via cp.async.bulk from tile-major swizzled layout.
template <bool SECOND>
__global__ __launch_bounds__(THREADS, 2)
void bt_gemm(const float* __restrict__ X,
             const __nv_bfloat16* __restrict__ Ain,   // tiled (xb or midb)
             const __nv_bfloat16* __restrict__ Wb,    // tiled weights
             const float* __restrict__ beff,
             const float* __restrict__ gamma,
             const float* __restrict__ beta,
             float* __restrict__ Out,
             __nv_bfloat16* __restrict__ MidOut) {    // tiled (layer1 output)
    extern __shared__ char smem[];
    const uint32_t sb = (uint32_t)__cvta_generic_to_shared(smem);

    const int tid  = threadIdx.x;
    const int warp = tid >> 5;
    const int lane = tid & 31;

    const int ng = blockIdx.x;            // 0..31  (partition*4 + n-tile)
    const int mt = blockIdx.y;            // 0..127
    const int p  = ng >> 2;
    const int nt = ng & 3;

    const int row0  = mt * BM;
    const int gcol0 = p * DDIM + nt * BN;

    // mbarriers: full[s] at sb + 8*s
    if (tid == 0) {
        MBARRIER_INIT(sb + 0, 1);
        MBARRIER_INIT(sb + 8, 1);
        MBARRIER_INIT(sb + 16, 1);
    }
    __syncthreads();

    const char* Abase = reinterpret_cast<const char*>(Ain) +
                        ((size_t)(mt * NPART + p) * NCHUNK) * TILE_BYTES;
    const char* Bbase = reinterpret_cast<const char*>(Wb) +
                        ((size_t)(p * 4 + nt) * NCHUNK) * TILE_BYTES;

    auto issue = [&](int s, int kc) {
        uint32_t mb = sb + 8 * s;
        uint32_t a_st = sb + SMEM_STAGE0 + s * STAGE_BYTES;
        MBARRIER_EXPECT_TX(mb, STAGE_BYTES);
        CP_BULK_G2S(a_st, Abase + (size_t)kc * TILE_BYTES, TILE_BYTES, mb);
        CP_BULK_G2S(a_st + TILE_BYTES, Bbase + (size_t)kc * TILE_BYTES, TILE_BYTES, mb);
    };

    if (tid == 0) { issue(0, 0); issue(1, 1); }

    // Warp layout: 4 (M) x 2 (N); warp tile 32x64
    const int wm = (warp >> 1) * 32;
    const int wn = (warp & 1) * 64;
    const int bh = wn >> 6;                       // B half (0 or 1), constant/warp

    const int a_row  = wm + (lane & 15);          // + im*16
    const int a_cb   = (lane >> 4) * 16;          // byte offset within row (+2*kk)
    const int b_row  = lane & 15;                 // + kk
    const int b_nb   = ((lane >> 4) * 8) * 2;     // byte (+ np*32)

    float acc[2][8][4];
    #pragma unroll
    for (int i = 0; i < 2; i++)
        #pragma unroll
        for (int j = 0; j < 8; j++)
            #pragma unroll
            for (int k = 0; k < 4; k++) acc[i][j][k] = 0.0f;

    #pragma unroll
    for (int kc = 0; kc < NCHUNK; kc++) {
        const int s = kc % STAGES;
        if (tid == 0 && kc + 2 < NCHUNK) issue((kc + 2) % STAGES, kc + 2);

        MBARRIER_WAIT_PARITY(sb + 8 * s, (kc / 3) & 1);

        const uint32_t a_st = sb + SMEM_STAGE0 + s * STAGE_BYTES;
        const uint32_t b_st = a_st + TILE_BYTES + bh * 8192;
        #pragma unroll
        for (int kk = 0; kk < BK; kk += 16) {
            uint32_t af[2][4];
            #pragma unroll
            for (int im = 0; im < 2; im++) {
                int r = a_row + im * 16;
                uint32_t addr = a_st + r * 128 +
                                (uint32_t)((kk * 2 + a_cb) ^ ((r & 7) * 16));
                ldsm_x4(af[im][0], af[im][1], af[im][2], af[im][3], addr);
            }
            #pragma unroll
            for (int np = 0; np < 4; np++) {
                int r = kk + b_row;
                uint32_t addr = b_st + r * 128 +
                                (uint32_t)((np * 32 + b_nb) ^ ((r & 7) * 16));
                uint32_t b0, b1, b2, b3;
                ldsm_x4_t(b0, b1, b2, b3, addr);
                #pragma unroll
                for (int im = 0; im < 2; im++) {
                    mma_bf16(acc[im][np * 2 + 0], af[im], b0, b1);
                    mma_bf16(acc[im][np * 2 + 1], af[im], b2, b3);
                }
            }
        }
        __syncthreads();   // all warps done with stage s -> safe to reissue
    }

    // ---- epilogue: v = acc + beff; parametric swish; (+residual)
    const int g  = lane >> 2;
    const int t2 = (lane & 3) << 1;
    #pragma unroll
    for (int im = 0; im < 2; im++) {
        #pragma unroll
        for (int n_ = 0; n_ < 8; n_++) {
            const int rowA = row0 + wm + im * 16 + g;
            const int col  = gcol0 + wn + n_ * 8 + t2;
            const float be0 = beff[col],  be1 = beff[col + 1];
            const float gm0 = gamma[col], gm1 = gamma[col + 1];
            const float bt0 = beta[col],  bt1 = beta[col + 1];
            #pragma unroll
            for (int h = 0; h < 2; h++) {
                const int rg = rowA + h * 8;
                float v0 = acc[im][n_][h * 2 + 0] + be0;
                float v1 = acc[im][n_][h * 2 + 1] + be1;
                const float s0 = 1.0f / (1.0f + __expf(-bt0 * v0));
                const float s1 = 1.0f / (1.0f + __expf(-bt1 * v1));
                float o0 = (gm0 + s0 * (1.0f - gm0)) * v0;
                float o1 = (gm1 + s1 * (1.0f - gm1)) * v1;
                if (SECOND) {
                    const float2 rx = *reinterpret_cast<const float2*>(
                        &X[(size_t)rg * IN_SIZE + col]);
                    *reinterpret_cast<float2*>(&Out[(size_t)rg * IN_SIZE + col]) =
                        make_float2(o0 + rx.x, o1 + rx.y);
                } else {
                    // write tiled+swizzled bf16 for layer-2's A
                    int r  = rg & 127;
                    int k2 = col & 511;            // within-partition col
                    int kc2 = k2 >> 6, cc = k2 & 63;
                    size_t tile = ((size_t)(mt * NPART + p) * NCHUNK + kc2) *
                                  TILE_BYTES;
                    uint32_t off = r * 128 +
                                   (uint32_t)((cc * 2) ^ ((r & 7) * 16));
                    *reinterpret_cast<__nv_bfloat162*>(
                        reinterpret_cast<char*>(MidOut) + tile + off) =
                        __floats2bfloat162_rn(v0 * 0.0f + o0, o1);  // plain store
                }
            }
        }
    }
}

// ---------------------------------------------------------------------------
extern "C" void kernel_launch(void* const* d_in, const int* in_sizes, int n_in,
                              void* d_out, int out_size) {
    (void)in_sizes; (void)n_in; (void)out_size;
    const float* x      = (const float*)d_in[0];
    const float* w1     = (const float*)d_in[1];
    const float* b1     = (const float*)d_in[2];
    const float* w2     = (const float*)d_in[3];
    const float* b2     = (const float*)d_in[4];
    const float* gamma1 = (const float*)d_in[5];
    const float* beta1  = (const float*)d_in[6];
    const float* gamma3 = (const float*)d_in[7];
    const float* beta3  = (const float*)d_in[8];
    const float* gain1  = (const float*)d_in[9];
    const float* nbias1 = (const float*)d_in[10];
    const float* gain3  = (const float*)d_in[11];
    const float* nbias3 = (const float*)d_in[12];
    float* out = (float*)d_out;

    __nv_bfloat16 *xb, *midb, *w1b, *w2b;
    float *beff1, *beff2;
    cudaGetSymbolAddress((void**)&xb,    g_xb);
    cudaGetSymbolAddress((void**)&midb,  g_midb);
    cudaGetSymbolAddress((void**)&w1b,   g_w1b);
    cudaGetSymbolAddress((void**)&w2b,   g_w2b);
    cudaGetSymbolAddress((void**)&beff1, g_beff1);
    cudaGetSymbolAddress((void**)&beff2, g_beff2);

    cudaFuncSetAttribute(bt_gemm<false>,
                         cudaFuncAttributeMaxDynamicSharedMemorySize, SMEM_TOTAL);
    cudaFuncSetAttribute(bt_gemm<true>,
                         cudaFuncAttributeMaxDynamicSharedMemorySize, SMEM_TOTAL);

    // Preprocess: tiled/swizzled bf16 weights (gain folded) + x; effective bias.
    convw_kernel<<<1024, 256>>>(w1, gain1, w1b);
    convw_kernel<<<1024, 256>>>(w2, gain3, w2b);
    convx_kernel<<<32768, 256>>>(x, xb);
    beff_kernel<<<128, 256>>>(w1, b1, nbias1, beff1);
    beff_kernel<<<128, 256>>>(w2, b2, nbias3, beff2);

    dim3 grid(32, 128);
    dim3 block(THREADS);

    bt_gemm<false><<<grid, block, SMEM_TOTAL>>>(x, xb,   w1b, beff1, gamma1, beta1, out, midb);
    bt_gemm<true ><<<grid, block, SMEM_TOTAL>>>(x, midb, w2b, beff2, gamma3, beta3, out, midb);
}

// round 8
// speedup vs baseline: 2.4060x; 1.0195x over previous
#include <cuda_runtime.h>
#include <cuda_bf16.h>
#include <cstdint>

#define BATCH   16384
#define IN_SIZE 4096
#define NPART   8
#define DDIM    512

#define BM 128
#define BN 128
#define BK 64
#define THREADS 256
#define NCHUNK (DDIM / BK)       // 8
#define STAGES 3

#define TILE_BYTES   16384       // one 16KB operand tile (A: 128x64 bf16, B: 64x128 bf16)
#define STAGE_BYTES  (2 * TILE_BYTES)
#define SMEM_STAGE0  1024
#define SMEM_TOTAL   (SMEM_STAGE0 + STAGES * STAGE_BYTES)   // 99328

// Device-global scratch (allocation APIs forbidden).
// xb/midb: tile-major swizzled bf16 activations. tile index = (mt*8+p)*8+kc
// w1b/w2b: tile-major swizzled bf16 weights.     tile index = (p*4+nt)*8+kc
__device__ __align__(16) __nv_bfloat16 g_xb  [(size_t)BATCH * IN_SIZE];
__device__ __align__(16) __nv_bfloat16 g_midb[(size_t)BATCH * IN_SIZE];
__device__ __align__(16) __nv_bfloat16 g_w1b [(size_t)NPART * DDIM * DDIM];
__device__ __align__(16) __nv_bfloat16 g_w2b [(size_t)NPART * DDIM * DDIM];
__device__ float g_beff1[IN_SIZE];
__device__ float g_beff2[IN_SIZE];

// ---------------------------------------------------------------------------
#define MBARRIER_INIT(addr, cnt) \
    asm volatile("mbarrier.init.shared.b64 [%0], %1;" :: "r"(addr), "r"(cnt) : "memory")
#define MBARRIER_EXPECT_TX(addr, bytes) \
    asm volatile("mbarrier.arrive.expect_tx.shared.b64 _, [%0], %1;" \
                 :: "r"(addr), "r"(bytes) : "memory")
#define MBARRIER_WAIT_PARITY(mbar, par) do {                                   \
    uint32_t _m = (mbar); uint32_t _p = (par); uint32_t _done;                 \
    asm volatile("{\n\t.reg .pred p;\n\t"                                      \
        "mbarrier.try_wait.parity.acquire.cta.shared::cta.b64 p, [%1], %2;\n\t"\
        "selp.b32 %0, 1, 0, p;\n\t}"                                           \
        : "=r"(_done) : "r"(_m), "r"(_p) : "memory");                          \
    if (!_done) {                                                              \
        asm volatile("{\n\t.reg .pred P1;\n\t"                                 \
            "WAIT_LOOP_%=:\n\t"                                                \
            "mbarrier.try_wait.parity.acquire.cta.shared::cta.b64 P1, [%0], %1, 0x989680;\n\t" \
            "@P1 bra.uni WAIT_DONE_%=;\n\t"                                    \
            "bra.uni WAIT_LOOP_%=;\n\t"                                        \
            "WAIT_DONE_%=:\n\t}"                                               \
            :: "r"(_m), "r"(_p) : "memory");                                   \
    }                                                                          \
} while (0)

// Bulk async copy global->shared (UBLKCP). sm_90 baseline PTX (not 'a'-gated).
#define CP_BULK_G2S(dst, src, bytes, mbar) \
    asm volatile("cp.async.bulk.shared::cluster.global.mbarrier::complete_tx::bytes " \
                 "[%0], [%1], %2, [%3];" \
                 :: "r"(dst), "l"(src), "r"(bytes), "r"(mbar) : "memory")

__device__ __forceinline__ void ldsm_x4(uint32_t* r, uint32_t addr) {
    asm volatile("ldmatrix.sync.aligned.m8n8.x4.shared.b16 {%0,%1,%2,%3}, [%4];"
                 : "=r"(r[0]), "=r"(r[1]), "=r"(r[2]), "=r"(r[3]) : "r"(addr));
}
__device__ __forceinline__ void ldsm_x4_t(uint32_t* r, uint32_t addr) {
    asm volatile("ldmatrix.sync.aligned.m8n8.x4.trans.shared.b16 {%0,%1,%2,%3}, [%4];"
                 : "=r"(r[0]), "=r"(r[1]), "=r"(r[2]), "=r"(r[3]) : "r"(addr));
}
__device__ __forceinline__ void mma_bf16(float c[4], const uint32_t a[4],
                                         uint32_t b0, uint32_t b1) {
    asm volatile(
        "mma.sync.aligned.m16n8k16.row.col.f32.bf16.bf16.f32 "
        "{%0,%1,%2,%3}, {%4,%5,%6,%7}, {%8,%9}, {%0,%1,%2,%3};"
        : "+f"(c[0]), "+f"(c[1]), "+f"(c[2]), "+f"(c[3])
        : "r"(a[0]), "r"(a[1]), "r"(a[2]), "r"(a[3]), "r"(b0), "r"(b1));
}

// ---------------------------------------------------------------------------
// bias_eff[c] = bias[c] + nb * colsum(W)[c]
__global__ void beff_kernel(const float* __restrict__ W,
                            const float* __restrict__ bias,
                            const float* __restrict__ nb,
                            float* __restrict__ beff) {
    int gid = blockIdx.x * blockDim.x + threadIdx.x;
    int c = gid >> 3;
    int s = gid & 7;
    int p = c >> 9;
    int col = c & 511;
    const float* Wp = W + (size_t)p * DDIM * DDIM + col;
    float sum = 0.f;
    int k0 = s * 64;
    #pragma unroll 8
    for (int k = k0; k < k0 + 64; k++) sum += Wp[(size_t)k * DDIM];
    #pragma unroll
    for (int m = 4; m >= 1; m >>= 1) sum += __shfl_xor_sync(0xFFFFFFFFu, sum, m);
    if (s == 0) beff[c] = bias[c] + nb[0] * sum;
}

// W * gain -> bf16, tiled+swizzled. B tile for (p,nt,kc): 64 K-rows x 128 N-cols,
// stored as two 64x64 halves; off = h*8192 + kk*128 + ((nn*2) ^ ((kk&7)*16)).
__global__ void convw_kernel(const float* __restrict__ W,
                             const float* __restrict__ gain_p,
                             __nv_bfloat16* __restrict__ Wb) {
    const float gain = gain_p[0];
    int gid = blockIdx.x * blockDim.x + threadIdx.x;   // 0..262143, 8 elems each
    int n0  = (gid & 63) * 8;        // 0..504 within partition (8-aligned)
    int k   = (gid >> 6) & 511;
    int p   = gid >> 15;

    const float* src = W + ((size_t)p * DDIM + k) * DDIM + n0;
    float4 v0 = *reinterpret_cast<const float4*>(src);
    float4 v1 = *reinterpret_cast<const float4*>(src + 4);
    __nv_bfloat162 o[4];
    o[0] = __floats2bfloat162_rn(v0.x * gain, v0.y * gain);
    o[1] = __floats2bfloat162_rn(v0.z * gain, v0.w * gain);
    o[2] = __floats2bfloat162_rn(v1.x * gain, v1.y * gain);
    o[3] = __floats2bfloat162_rn(v1.z * gain, v1.w * gain);

    int kc = k >> 6, kk = k & 63;
    int nt = n0 >> 7, h = (n0 >> 6) & 1, nn = n0 & 63;
    size_t tile = ((size_t)(p * 4 + nt) * NCHUNK + kc) * TILE_BYTES;
    uint32_t off = h * 8192 + kk * 128 + (uint32_t)((nn * 2) ^ ((kk & 7) * 16));
    *reinterpret_cast<uint4*>(reinterpret_cast<char*>(Wb) + tile + off) =
        *reinterpret_cast<uint4*>(o);
}

// x -> bf16, tiled+swizzled. A tile for (mt,p,kc): 128 rows x 64 K-cols;
// off = r*128 + ((c*2) ^ ((r&7)*16)).
__global__ void convx_kernel(const float* __restrict__ X,
                             __nv_bfloat16* __restrict__ Xb) {
    int gid = blockIdx.x * blockDim.x + threadIdx.x;
    int c0  = (gid & 63) * 8;
    int prow = gid >> 6;
    int p   = prow & 7;
    int row = prow >> 3;

    const float* src = X + (size_t)row * IN_SIZE + p * DDIM + c0;
    float4 v0 = *reinterpret_cast<const float4*>(src);
    float4 v1 = *reinterpret_cast<const float4*>(src + 4);
    __nv_bfloat162 o[4];
    o[0] = __floats2bfloat162_rn(v0.x, v0.y);
    o[1] = __floats2bfloat162_rn(v0.z, v0.w);
    o[2] = __floats2bfloat162_rn(v1.x, v1.y);
    o[3] = __floats2bfloat162_rn(v1.z, v1.w);

    int mt = row >> 7, r = row & 127;
    int kc = c0 >> 6, c = c0 & 63;
    size_t tile = ((size_t)(mt * NPART + p) * NCHUNK + kc) * TILE_BYTES;
    uint32_t off = r * 128 + (uint32_t)((c * 2) ^ ((r & 7) * 16));
    *reinterpret_cast<uint4*>(reinterpret_cast<char*>(Xb) + tile + off) =
        *reinterpret_cast<uint4*>(o);
}

// ---------------------------------------------------------------------------
// One layer GEMM: Out = swish( A @ W_eff_p + beff, gamma, beta ) [+ X residual]
template <bool SECOND>
__global__ __launch_bounds__(THREADS, 2)
void bt_gemm(const float* __restrict__ X,
             const __nv_bfloat16* __restrict__ Ain,   // tiled (xb or midb)
             const __nv_bfloat16* __restrict__ Wb,    // tiled weights
             const float* __restrict__ beff,
             const float* __restrict__ gamma,
             const float* __restrict__ beta,
             float* __restrict__ Out,
             __nv_bfloat16* __restrict__ MidOut) {    // tiled (layer1 output)
    extern __shared__ char smem[];
    const uint32_t sb = (uint32_t)__cvta_generic_to_shared(smem);

    const int tid  = threadIdx.x;
    const int warp = tid >> 5;
    const int lane = tid & 31;

    const int ng = blockIdx.x;            // 0..31  (partition*4 + n-tile)
    const int mt = blockIdx.y;            // 0..127
    const int p  = ng >> 2;
    const int nt = ng & 3;

    const int row0  = mt * BM;
    const int gcol0 = p * DDIM + nt * BN;

    if (tid == 0) {
        MBARRIER_INIT(sb + 0, 1);
        MBARRIER_INIT(sb + 8, 1);
        MBARRIER_INIT(sb + 16, 1);
    }
    __syncthreads();

    const char* Abase = reinterpret_cast<const char*>(Ain) +
                        ((size_t)(mt * NPART + p) * NCHUNK) * TILE_BYTES;
    const char* Bbase = reinterpret_cast<const char*>(Wb) +
                        ((size_t)(p * 4 + nt) * NCHUNK) * TILE_BYTES;

    auto issue = [&](int s, int kc) {
        uint32_t mb = sb + 8 * s;
        uint32_t a_st = sb + SMEM_STAGE0 + s * STAGE_BYTES;
        MBARRIER_EXPECT_TX(mb, STAGE_BYTES);
        CP_BULK_G2S(a_st, Abase + (size_t)kc * TILE_BYTES, TILE_BYTES, mb);
        CP_BULK_G2S(a_st + TILE_BYTES, Bbase + (size_t)kc * TILE_BYTES, TILE_BYTES, mb);
    };

    if (tid == 0) { issue(0, 0); issue(1, 1); }

    // Warp layout: 4 (M) x 2 (N); warp tile 32x64
    const int wm = (warp >> 1) * 32;
    const int wn = (warp & 1) * 64;
    const int bh = wn >> 6;

    const int a_row  = wm + (lane & 15);          // + im*16
    const int a_cb   = (lane >> 4) * 16;          // byte offset within row (+2*kk)
    const int b_row  = lane & 31 & 15;            // lane & 15
    const int b_nb   = (lane >> 4) * 16;          // byte (+ np*32)

    float acc[2][8][4];
    #pragma unroll
    for (int i = 0; i < 2; i++)
        #pragma unroll
        for (int j = 0; j < 8; j++)
            #pragma unroll
            for (int k = 0; k < 4; k++) acc[i][j][k] = 0.0f;

    uint32_t af[2][2][4];   // [kk-parity][im][frag]
    uint32_t bb[2][4];      // [np-parity][frag]

    #pragma unroll
    for (int kc = 0; kc < NCHUNK; kc++) {
        const int s = kc % STAGES;
        if (tid == 0 && kc + 2 < NCHUNK) issue((kc + 2) % STAGES, kc + 2);

        MBARRIER_WAIT_PARITY(sb + 8 * s, (kc / 3) & 1);

        const uint32_t a_st = sb + SMEM_STAGE0 + s * STAGE_BYTES;
        const uint32_t b_st = a_st + TILE_BYTES + bh * 8192;

        // address helpers (byte math; swizzle bits [6:4] ^= row&7)
        auto a_addr = [&](int kk, int im) -> uint32_t {
            int r = a_row + im * 16;
            return a_st + r * 128 + (uint32_t)((kk * 2 + a_cb) ^ ((r & 7) * 16));
        };
        auto b_addr = [&](int kk, int np) -> uint32_t {
            int r = kk + b_row;
            return b_st + r * 128 + (uint32_t)((np * 32 + b_nb) ^ ((r & 7) * 16));
        };

        // chunk prologue: A(kk=0) both im, B(kk=0, np=0)
        ldsm_x4(af[0][0], a_addr(0, 0));
        ldsm_x4(af[0][1], a_addr(0, 1));
        ldsm_x4_t(bb[0], b_addr(0, 0));

        #pragma unroll
        for (int ki = 0; ki < 4; ki++) {
            const int kk = ki * 16;
            const int pa = ki & 1;
            #pragma unroll
            for (int np = 0; np < 4; np++) {
                const int cb = np & 1;
                // prefetch next fragments before consuming current ones
                if (np < 3) {
                    ldsm_x4_t(bb[cb ^ 1], b_addr(kk, np + 1));
                } else if (ki < 3) {
                    ldsm_x4_t(bb[cb ^ 1], b_addr(kk + 16, 0));
                    ldsm_x4(af[pa ^ 1][0], a_addr(kk + 16, 0));
                    ldsm_x4(af[pa ^ 1][1], a_addr(kk + 16, 1));
                }
                mma_bf16(acc[0][np * 2 + 0], af[pa][0], bb[cb][0], bb[cb][1]);
                mma_bf16(acc[0][np * 2 + 1], af[pa][0], bb[cb][2], bb[cb][3]);
                mma_bf16(acc[1][np * 2 + 0], af[pa][1], bb[cb][0], bb[cb][1]);
                mma_bf16(acc[1][np * 2 + 1], af[pa][1], bb[cb][2], bb[cb][3]);
            }
        }
        __syncthreads();   // all warps done with stage s -> safe to reissue
    }

    // ---- epilogue: v = acc + beff; parametric swish; (+residual)
    const int g  = lane >> 2;
    const int t2 = (lane & 3) << 1;
    #pragma unroll
    for (int im = 0; im < 2; im++) {
        #pragma unroll
        for (int n_ = 0; n_ < 8; n_++) {
            const int rowA = row0 + wm + im * 16 + g;
            const int col  = gcol0 + wn + n_ * 8 + t2;
            const float be0 = beff[col],  be1 = beff[col + 1];
            const float gm0 = gamma[col], gm1 = gamma[col + 1];
            const float bt0 = beta[col],  bt1 = beta[col + 1];
            #pragma unroll
            for (int h = 0; h < 2; h++) {
                const int rg = rowA + h * 8;
                float v0 = acc[im][n_][h * 2 + 0] + be0;
                float v1 = acc[im][n_][h * 2 + 1] + be1;
                const float s0 = 1.0f / (1.0f + __expf(-bt0 * v0));
                const float s1 = 1.0f / (1.0f + __expf(-bt1 * v1));
                float o0 = (gm0 + s0 * (1.0f - gm0)) * v0;
                float o1 = (gm1 + s1 * (1.0f - gm1)) * v1;
                if (SECOND) {
                    const float2 rx = *reinterpret_cast<const float2*>(
                        &X[(size_t)rg * IN_SIZE + col]);
                    *reinterpret_cast<float2*>(&Out[(size_t)rg * IN_SIZE + col]) =
                        make_float2(o0 + rx.x, o1 + rx.y);
                } else {
                    // write tiled+swizzled bf16 for layer-2's A
                    int r  = rg & 127;
                    int k2 = col & 511;
                    int kc2 = k2 >> 6, cc = k2 & 63;
                    size_t tile = ((size_t)(mt * NPART + p) * NCHUNK + kc2) *
                                  TILE_BYTES;
                    uint32_t off = r * 128 +
                                   (uint32_t)((cc * 2) ^ ((r & 7) * 16));
                    *reinterpret_cast<__nv_bfloat162*>(
                        reinterpret_cast<char*>(MidOut) + tile + off) =
                        __floats2bfloat162_rn(o0, o1);
                }
            }
        }
    }
}

// ---------------------------------------------------------------------------
extern "C" void kernel_launch(void* const* d_in, const int* in_sizes, int n_in,
                              void* d_out, int out_size) {
    (void)in_sizes; (void)n_in; (void)out_size;
    const float* x      = (const float*)d_in[0];
    const float* w1     = (const float*)d_in[1];
    const float* b1     = (const float*)d_in[2];
    const float* w2     = (const float*)d_in[3];
    const float* b2     = (const float*)d_in[4];
    const float* gamma1 = (const float*)d_in[5];
    const float* beta1  = (const float*)d_in[6];
    const float* gamma3 = (const float*)d_in[7];
    const float* beta3  = (const float*)d_in[8];
    const float* gain1  = (const float*)d_in[9];
    const float* nbias1 = (const float*)d_in[10];
    const float* gain3  = (const float*)d_in[11];
    const float* nbias3 = (const float*)d_in[12];
    float* out = (float*)d_out;

    __nv_bfloat16 *xb, *midb, *w1b, *w2b;
    float *beff1, *beff2;
    cudaGetSymbolAddress((void**)&xb,    g_xb);
    cudaGetSymbolAddress((void**)&midb,  g_midb);
    cudaGetSymbolAddress((void**)&w1b,   g_w1b);
    cudaGetSymbolAddress((void**)&w2b,   g_w2b);
    cudaGetSymbolAddress((void**)&beff1, g_beff1);
    cudaGetSymbolAddress((void**)&beff2, g_beff2);

    cudaFuncSetAttribute(bt_gemm<false>,
                         cudaFuncAttributeMaxDynamicSharedMemorySize, SMEM_TOTAL);
    cudaFuncSetAttribute(bt_gemm<true>,
                         cudaFuncAttributeMaxDynamicSharedMemorySize, SMEM_TOTAL);

    dim3 grid(32, 128);
    dim3 block(THREADS);

    // Launch order chosen so gemm1 is the 5th app launch (ncu -s 5 visibility),
    // with all dependencies (convx, convw1, beff1) before it.
    convx_kernel<<<32768, 256>>>(x, xb);
    convw_kernel<<<1024, 256>>>(w1, gain1, w1b);
    beff_kernel<<<128, 256>>>(w1, b1, nbias1, beff1);
    convw_kernel<<<1024, 256>>>(w2, gain3, w2b);
    bt_gemm<false><<<grid, block, SMEM_TOTAL>>>(x, xb,   w1b, beff1, gamma1, beta1, out, midb);
    beff_kernel<<<128, 256>>>(w2, b2, nbias3, beff2);
    bt_gemm<true ><<<grid, block, SMEM_TOTAL>>>(x, midb, w2b, beff2, gamma3, beta3, out, midb);
}

// round 9
// speedup vs baseline: 2.4909x; 1.0353x over previous
#include <cuda_runtime.h>
#include <cuda_bf16.h>
#include <cstdint>

#define BATCH   16384
#define IN_SIZE 4096
#define NPART   8
#define DDIM    512

#define BM 128
#define BN 128
#define BK 64
#define THREADS 256
#define NCHUNK (DDIM / BK)       // 8
#define STAGES 3

#define TILE_BYTES   16384       // one 16KB operand tile (A: 128x64 bf16, B: 64x128 bf16)
#define STAGE_BYTES  (2 * TILE_BYTES)
#define SMEM_STAGE0  1024
#define SMEM_TOTAL   (SMEM_STAGE0 + STAGES * STAGE_BYTES)   // 99328

// Device-global scratch (allocation APIs forbidden).
__device__ __align__(16) __nv_bfloat16 g_xb  [(size_t)BATCH * IN_SIZE];
__device__ __align__(16) __nv_bfloat16 g_midb[(size_t)BATCH * IN_SIZE];
__device__ __align__(16) __nv_bfloat16 g_w1b [(size_t)NPART * DDIM * DDIM];
__device__ __align__(16) __nv_bfloat16 g_w2b [(size_t)NPART * DDIM * DDIM];
__device__ float g_beff1[IN_SIZE];
__device__ float g_beff2[IN_SIZE];

// ---------------------------------------------------------------------------
#define MBARRIER_INIT(addr, cnt) \
    asm volatile("mbarrier.init.shared.b64 [%0], %1;" :: "r"(addr), "r"(cnt) : "memory")
#define MBARRIER_EXPECT_TX(addr, bytes) \
    asm volatile("mbarrier.arrive.expect_tx.shared.b64 _, [%0], %1;" \
                 :: "r"(addr), "r"(bytes) : "memory")
#define MBARRIER_ARRIVE(addr) \
    asm volatile("mbarrier.arrive.shared.b64 _, [%0];" :: "r"(addr) : "memory")
#define MBARRIER_WAIT_PARITY(mbar, par) do {                                   \
    uint32_t _m = (mbar); uint32_t _p = (par); uint32_t _done;                 \
    asm volatile("{\n\t.reg .pred p;\n\t"                                      \
        "mbarrier.try_wait.parity.acquire.cta.shared::cta.b64 p, [%1], %2;\n\t"\
        "selp.b32 %0, 1, 0, p;\n\t}"                                           \
        : "=r"(_done) : "r"(_m), "r"(_p) : "memory");                          \
    if (!_done) {                                                              \
        asm volatile("{\n\t.reg .pred P1;\n\t"                                 \
            "WAIT_LOOP_%=:\n\t"                                                \
            "mbarrier.try_wait.parity.acquire.cta.shared::cta.b64 P1, [%0], %1, 0x989680;\n\t" \
            "@P1 bra.uni WAIT_DONE_%=;\n\t"                                    \
            "bra.uni WAIT_LOOP_%=;\n\t"                                        \
            "WAIT_DONE_%=:\n\t}"                                               \
            :: "r"(_m), "r"(_p) : "memory");                                   \
    }                                                                          \
} while (0)

// Bulk async copy global->shared (UBLKCP). sm_90 baseline PTX (not 'a'-gated).
#define CP_BULK_G2S(dst, src, bytes, mbar) \
    asm volatile("cp.async.bulk.shared::cluster.global.mbarrier::complete_tx::bytes " \
                 "[%0], [%1], %2, [%3];" \
                 :: "r"(dst), "l"(src), "r"(bytes), "r"(mbar) : "memory")

__device__ __forceinline__ void ldsm_x4(uint32_t* r, uint32_t addr) {
    asm volatile("ldmatrix.sync.aligned.m8n8.x4.shared.b16 {%0,%1,%2,%3}, [%4];"
                 : "=r"(r[0]), "=r"(r[1]), "=r"(r[2]), "=r"(r[3]) : "r"(addr));
}
__device__ __forceinline__ void ldsm_x4_t(uint32_t* r, uint32_t addr) {
    asm volatile("ldmatrix.sync.aligned.m8n8.x4.trans.shared.b16 {%0,%1,%2,%3}, [%4];"
                 : "=r"(r[0]), "=r"(r[1]), "=r"(r[2]), "=r"(r[3]) : "r"(addr));
}
__device__ __forceinline__ void mma_bf16(float c[4], const uint32_t a[4],
                                         uint32_t b0, uint32_t b1) {
    asm volatile(
        "mma.sync.aligned.m16n8k16.row.col.f32.bf16.bf16.f32 "
        "{%0,%1,%2,%3}, {%4,%5,%6,%7}, {%8,%9}, {%0,%1,%2,%3};"
        : "+f"(c[0]), "+f"(c[1]), "+f"(c[2]), "+f"(c[3])
        : "r"(a[0]), "r"(a[1]), "r"(a[2]), "r"(a[3]), "r"(b0), "r"(b1));
}

// ---------------------------------------------------------------------------
// bias_eff[col] = bias[col] + nb * colsum(W)[col]  — coalesced version.
// grid = 16 blocks (p*2 + half), block = 1024 threads (256 cols x 4 k-slices)
__global__ void beff_kernel(const float* __restrict__ W,
                            const float* __restrict__ bias,
                            const float* __restrict__ nb,
                            float* __restrict__ beff) {
    __shared__ float part[4][256];
    const int p    = blockIdx.x >> 1;
    const int half = blockIdx.x & 1;
    const int c    = threadIdx.x & 255;
    const int ks   = threadIdx.x >> 8;
    const int col  = half * 256 + c;

    const float* Wp = W + (size_t)p * DDIM * DDIM + col;
    float sum = 0.f;
    const int k0 = ks * 128;
    #pragma unroll 8
    for (int k = k0; k < k0 + 128; k++) sum += Wp[(size_t)k * DDIM];
    part[ks][c] = sum;
    __syncthreads();
    if (ks == 0) {
        float s = part[0][c] + part[1][c] + part[2][c] + part[3][c];
        beff[p * DDIM + col] = bias[p * DDIM + col] + nb[0] * s;
    }
}

// W * gain -> bf16, tiled+swizzled. B tile for (p,nt,kc): 64 K-rows x 128 N-cols,
// stored as two 64x64 halves; off = h*8192 + kk*128 + ((nn*2) ^ ((kk&7)*16)).
__global__ void convw_kernel(const float* __restrict__ W,
                             const float* __restrict__ gain_p,
                             __nv_bfloat16* __restrict__ Wb) {
    const float gain = gain_p[0];
    int gid = blockIdx.x * blockDim.x + threadIdx.x;   // 0..262143, 8 elems each
    int n0  = (gid & 63) * 8;
    int k   = (gid >> 6) & 511;
    int p   = gid >> 15;

    const float* src = W + ((size_t)p * DDIM + k) * DDIM + n0;
    float4 v0 = *reinterpret_cast<const float4*>(src);
    float4 v1 = *reinterpret_cast<const float4*>(src + 4);
    __nv_bfloat162 o[4];
    o[0] = __floats2bfloat162_rn(v0.x * gain, v0.y * gain);
    o[1] = __floats2bfloat162_rn(v0.z * gain, v0.w * gain);
    o[2] = __floats2bfloat162_rn(v1.x * gain, v1.y * gain);
    o[3] = __floats2bfloat162_rn(v1.z * gain, v1.w * gain);

    int kc = k >> 6, kk = k & 63;
    int nt = n0 >> 7, h = (n0 >> 6) & 1, nn = n0 & 63;
    size_t tile = ((size_t)(p * 4 + nt) * NCHUNK + kc) * TILE_BYTES;
    uint32_t off = h * 8192 + kk * 128 + (uint32_t)((nn * 2) ^ ((kk & 7) * 16));
    *reinterpret_cast<uint4*>(reinterpret_cast<char*>(Wb) + tile + off) =
        *reinterpret_cast<uint4*>(o);
}

// x -> bf16, tiled+swizzled. A tile for (mt,p,kc): 128 rows x 64 K-cols;
// off = r*128 + ((c*2) ^ ((r&7)*16)).
__global__ void convx_kernel(const float* __restrict__ X,
                             __nv_bfloat16* __restrict__ Xb) {
    int gid = blockIdx.x * blockDim.x + threadIdx.x;
    int c0  = (gid & 63) * 8;
    int prow = gid >> 6;
    int p   = prow & 7;
    int row = prow >> 3;

    const float* src = X + (size_t)row * IN_SIZE + p * DDIM + c0;
    float4 v0 = *reinterpret_cast<const float4*>(src);
    float4 v1 = *reinterpret_cast<const float4*>(src + 4);
    __nv_bfloat162 o[4];
    o[0] = __floats2bfloat162_rn(v0.x, v0.y);
    o[1] = __floats2bfloat162_rn(v0.z, v0.w);
    o[2] = __floats2bfloat162_rn(v1.x, v1.y);
    o[3] = __floats2bfloat162_rn(v1.z, v1.w);

    int mt = row >> 7, r = row & 127;
    int kc = c0 >> 6, c = c0 & 63;
    size_t tile = ((size_t)(mt * NPART + p) * NCHUNK + kc) * TILE_BYTES;
    uint32_t off = r * 128 + (uint32_t)((c * 2) ^ ((r & 7) * 16));
    *reinterpret_cast<uint4*>(reinterpret_cast<char*>(Xb) + tile + off) =
        *reinterpret_cast<uint4*>(o);
}

// ---------------------------------------------------------------------------
// One layer GEMM: Out = swish( A @ W_eff_p + beff, gamma, beta ) [+ X residual]
// Warp-decoupled pipeline: full[s] = bulk-copy completion, empty[s] = 8 warp
// arrivals after consuming stage s. No block-wide barriers in the mainloop.
template <bool SECOND>
__global__ __launch_bounds__(THREADS, 2)
void bt_gemm(const float* __restrict__ X,
             const __nv_bfloat16* __restrict__ Ain,   // tiled (xb or midb)
             const __nv_bfloat16* __restrict__ Wb,    // tiled weights
             const float* __restrict__ beff,
             const float* __restrict__ gamma,
             const float* __restrict__ beta,
             float* __restrict__ Out,
             __nv_bfloat16* __restrict__ MidOut) {    // tiled (layer1 output)
    extern __shared__ char smem[];
    const uint32_t sb = (uint32_t)__cvta_generic_to_shared(smem);

    const int tid  = threadIdx.x;
    const int warp = tid >> 5;
    const int lane = tid & 31;

    const int ng = blockIdx.x;            // 0..31  (partition*4 + n-tile)
    const int mt = blockIdx.y;            // 0..127
    const int p  = ng >> 2;
    const int nt = ng & 3;

    const int row0  = mt * BM;
    const int gcol0 = p * DDIM + nt * BN;

    // full[s] at sb + 8*s ; empty[s] at sb + 24 + 8*s
    if (tid == 0) {
        MBARRIER_INIT(sb + 0, 1);
        MBARRIER_INIT(sb + 8, 1);
        MBARRIER_INIT(sb + 16, 1);
        MBARRIER_INIT(sb + 24, 8);
        MBARRIER_INIT(sb + 32, 8);
        MBARRIER_INIT(sb + 40, 8);
    }
    __syncthreads();

    const char* Abase = reinterpret_cast<const char*>(Ain) +
                        ((size_t)(mt * NPART + p) * NCHUNK) * TILE_BYTES;
    const char* Bbase = reinterpret_cast<const char*>(Wb) +
                        ((size_t)(p * 4 + nt) * NCHUNK) * TILE_BYTES;

    auto issue = [&](int s, int kc) {
        uint32_t mb = sb + 8 * s;
        uint32_t a_st = sb + SMEM_STAGE0 + s * STAGE_BYTES;
        MBARRIER_EXPECT_TX(mb, STAGE_BYTES);
        CP_BULK_G2S(a_st, Abase + (size_t)kc * TILE_BYTES, TILE_BYTES, mb);
        CP_BULK_G2S(a_st + TILE_BYTES, Bbase + (size_t)kc * TILE_BYTES, TILE_BYTES, mb);
    };

    if (tid == 0) { issue(0, 0); issue(1, 1); }

    // Warp layout: 4 (M) x 2 (N); warp tile 32x64
    const int wm = (warp >> 1) * 32;
    const int wn = (warp & 1) * 64;
    const int bh = wn >> 6;

    const int a_row  = wm + (lane & 15);
    const int a_cb   = (lane >> 4) * 16;
    const int b_row  = lane & 15;
    const int b_nb   = (lane >> 4) * 16;

    float acc[2][8][4];
    #pragma unroll
    for (int i = 0; i < 2; i++)
        #pragma unroll
        for (int j = 0; j < 8; j++)
            #pragma unroll
            for (int k = 0; k < 4; k++) acc[i][j][k] = 0.0f;

    uint32_t af[2][2][4];   // [kk-parity][im][frag]
    uint32_t bb[2][4];      // [np-parity][frag]

    #pragma unroll
    for (int kc = 0; kc < NCHUNK; kc++) {
        const int s = kc % STAGES;

        // Producer: reissue stage (kc+2)%3 once every warp has consumed its
        // previous occupant (chunk kc-1).
        if (tid == 0 && kc + 2 < NCHUNK) {
            const int j = kc + 2;
            if (j >= STAGES)
                MBARRIER_WAIT_PARITY(sb + 24 + 8 * (j % STAGES), (((j - 3) / 3) & 1));
            issue(j % STAGES, j);
        }

        MBARRIER_WAIT_PARITY(sb + 8 * s, (kc / 3) & 1);

        const uint32_t a_st = sb + SMEM_STAGE0 + s * STAGE_BYTES;
        const uint32_t b_st = a_st + TILE_BYTES + bh * 8192;

        auto a_addr = [&](int kk, int im) -> uint32_t {
            int r = a_row + im * 16;
            return a_st + r * 128 + (uint32_t)((kk * 2 + a_cb) ^ ((r & 7) * 16));
        };
        auto b_addr = [&](int kk, int np) -> uint32_t {
            int r = kk + b_row;
            return b_st + r * 128 + (uint32_t)((np * 32 + b_nb) ^ ((r & 7) * 16));
        };

        ldsm_x4(af[0][0], a_addr(0, 0));
        ldsm_x4(af[0][1], a_addr(0, 1));
        ldsm_x4_t(bb[0], b_addr(0, 0));

        #pragma unroll
        for (int ki = 0; ki < 4; ki++) {
            const int kk = ki * 16;
            const int pa = ki & 1;
            #pragma unroll
            for (int np = 0; np < 4; np++) {
                const int cb = np & 1;
                if (np < 3) {
                    ldsm_x4_t(bb[cb ^ 1], b_addr(kk, np + 1));
                } else if (ki < 3) {
                    ldsm_x4_t(bb[cb ^ 1], b_addr(kk + 16, 0));
                    ldsm_x4(af[pa ^ 1][0], a_addr(kk + 16, 0));
                    ldsm_x4(af[pa ^ 1][1], a_addr(kk + 16, 1));
                }
                mma_bf16(acc[0][np * 2 + 0], af[pa][0], bb[cb][0], bb[cb][1]);
                mma_bf16(acc[0][np * 2 + 1], af[pa][0], bb[cb][2], bb[cb][3]);
                mma_bf16(acc[1][np * 2 + 0], af[pa][1], bb[cb][0], bb[cb][1]);
                mma_bf16(acc[1][np * 2 + 1], af[pa][1], bb[cb][2], bb[cb][3]);
            }
        }

        // Consumer arrival: this warp is done reading stage s.
        // Only needed while the stage will be reused (kc+3 < NCHUNK).
        if (kc <= 4 && lane == 0) MBARRIER_ARRIVE(sb + 24 + 8 * s);
    }

    // ---- epilogue: v = acc + beff; parametric swish; (+residual)
    const int g  = lane >> 2;
    const int t2 = (lane & 3) << 1;
    #pragma unroll
    for (int im = 0; im < 2; im++) {
        #pragma unroll
        for (int n_ = 0; n_ < 8; n_++) {
            const int rowA = row0 + wm + im * 16 + g;
            const int col  = gcol0 + wn + n_ * 8 + t2;
            const float be0 = beff[col],  be1 = beff[col + 1];
            const float gm0 = gamma[col], gm1 = gamma[col + 1];
            const float bt0 = beta[col],  bt1 = beta[col + 1];
            #pragma unroll
            for (int h = 0; h < 2; h++) {
                const int rg = rowA + h * 8;
                float v0 = acc[im][n_][h * 2 + 0] + be0;
                float v1 = acc[im][n_][h * 2 + 1] + be1;
                const float s0 = 1.0f / (1.0f + __expf(-bt0 * v0));
                const float s1 = 1.0f / (1.0f + __expf(-bt1 * v1));
                float o0 = (gm0 + s0 * (1.0f - gm0)) * v0;
                float o1 = (gm1 + s1 * (1.0f - gm1)) * v1;
                if (SECOND) {
                    const float2 rx = *reinterpret_cast<const float2*>(
                        &X[(size_t)rg * IN_SIZE + col]);
                    *reinterpret_cast<float2*>(&Out[(size_t)rg * IN_SIZE + col]) =
                        make_float2(o0 + rx.x, o1 + rx.y);
                } else {
                    int r  = rg & 127;
                    int k2 = col & 511;
                    int kc2 = k2 >> 6, cc = k2 & 63;
                    size_t tile = ((size_t)(mt * NPART + p) * NCHUNK + kc2) *
                                  TILE_BYTES;
                    uint32_t off = r * 128 +
                                   (uint32_t)((cc * 2) ^ ((r & 7) * 16));
                    *reinterpret_cast<__nv_bfloat162*>(
                        reinterpret_cast<char*>(MidOut) + tile + off) =
                        __floats2bfloat162_rn(o0, o1);
                }
            }
        }
    }
}

// ---------------------------------------------------------------------------
extern "C" void kernel_launch(void* const* d_in, const int* in_sizes, int n_in,
                              void* d_out, int out_size) {
    (void)in_sizes; (void)n_in; (void)out_size;
    const float* x      = (const float*)d_in[0];
    const float* w1     = (const float*)d_in[1];
    const float* b1     = (const float*)d_in[2];
    const float* w2     = (const float*)d_in[3];
    const float* b2     = (const float*)d_in[4];
    const float* gamma1 = (const float*)d_in[5];
    const float* beta1  = (const float*)d_in[6];
    const float* gamma3 = (const float*)d_in[7];
    const float* beta3  = (const float*)d_in[8];
    const float* gain1  = (const float*)d_in[9];
    const float* nbias1 = (const float*)d_in[10];
    const float* gain3  = (const float*)d_in[11];
    const float* nbias3 = (const float*)d_in[12];
    float* out = (float*)d_out;

    __nv_bfloat16 *xb, *midb, *w1b, *w2b;
    float *beff1, *beff2;
    cudaGetSymbolAddress((void**)&xb,    g_xb);
    cudaGetSymbolAddress((void**)&midb,  g_midb);
    cudaGetSymbolAddress((void**)&w1b,   g_w1b);
    cudaGetSymbolAddress((void**)&w2b,   g_w2b);
    cudaGetSymbolAddress((void**)&beff1, g_beff1);
    cudaGetSymbolAddress((void**)&beff2, g_beff2);

    cudaFuncSetAttribute(bt_gemm<false>,
                         cudaFuncAttributeMaxDynamicSharedMemorySize, SMEM_TOTAL);
    cudaFuncSetAttribute(bt_gemm<true>,
                         cudaFuncAttributeMaxDynamicSharedMemorySize, SMEM_TOTAL);

    dim3 grid(32, 128);
    dim3 block(THREADS);

    // Order: all preprocessing first; GEMMs are launches #6 and #7.
    convx_kernel<<<32768, 256>>>(x, xb);
    convw_kernel<<<1024, 256>>>(w1, gain1, w1b);
    beff_kernel<<<16, 1024>>>(w1, b1, nbias1, beff1);
    convw_kernel<<<1024, 256>>>(w2, gain3, w2b);
    beff_kernel<<<16, 1024>>>(w2, b2, nbias3, beff2);
    bt_gemm<false><<<grid, block, SMEM_TOTAL>>>(x, xb,   w1b, beff1, gamma1, beta1, out, midb);
    bt_gemm<true ><<<grid, block, SMEM_TOTAL>>>(x, midb, w2b, beff2, gamma3, beta3, out, midb);
}